// round 10
// baseline (speedup 1.0000x reference)
#include <cuda_runtime.h>
#include <cuda_fp16.h>

#define Nn 100000
#define MAXE 3200000
#define Gg 5000
#define BN_EPS 1e-5f

// ---------------- scratch (static device globals; zero-initialized at load) ----------------
__device__ int      g_deg [Nn];          // self-restoring: k_scan resets to 0 each call
__device__ int      g_row [Nn + 1];
__device__ int      g_cur [Nn];
__device__ int      g_csrc[MAXE];
__device__ float    g_dinv[Nn];
__device__ uint4    g_xh  [Nn * 4];     // x' = x*dinv, padded to 32 halfs
__device__ float    g_axp [Nn * 32];    // aggregated x', padded 32 floats
__device__ uint4    g_t2h [Nn * 4];     // t2' = bnrelu(acc1)@W2*dinv, 32 halfs
__device__ uint4    g_t3h [Nn * 2];     // t3' = bnrelu(acc2)@W3*dinv, 16 halfs
__device__ uint2    g_h3h [Nn * 4];     // h3 post-BN, 16 halfs
__device__ float    g_acc1[Nn * 64];
__device__ float    g_acc2[Nn * 32];
__device__ float    g_acc3[Nn * 16];
__device__ float    g_as  [Nn * 8];
__device__ float    g_ad  [Nn * 8];
__device__ float    g_was [16 * 8];
__device__ float    g_wad [16 * 8];
__device__ float    g_pool[Gg * 16];    // zeroed by k_scan each call
__device__ float    g_bn  [6 * 64];     // zeroed by k_scan each call

// ---------------- helpers ----------------
__device__ __forceinline__ void red4(float4* p, float4 v) {
    asm volatile("red.global.add.v4.f32 [%0], {%1,%2,%3,%4};"
                 :: "l"(p), "f"(v.x), "f"(v.y), "f"(v.z), "f"(v.w) : "memory");
}
__device__ __forceinline__ float leaky(float v) { return v > 0.f ? v : 0.2f * v; }
__device__ __forceinline__ void acc8(float* a, uint4 u) {
    const __half2* h = (const __half2*)&u;
    float2 f0 = __half22float2(h[0]); a[0] += f0.x; a[1] += f0.y;
    float2 f1 = __half22float2(h[1]); a[2] += f1.x; a[3] += f1.y;
    float2 f2 = __half22float2(h[2]); a[4] += f2.x; a[5] += f2.y;
    float2 f3 = __half22float2(h[3]); a[6] += f3.x; a[7] += f3.y;
}
// packed fp16 pairwise add (one HADD2 per half2 lane)
__device__ __forceinline__ uint4 hadd4(uint4 x, uint4 y) {
    uint4 r;
    asm("add.rn.f16x2 %0, %1, %2;" : "=r"(r.x) : "r"(x.x), "r"(y.x));
    asm("add.rn.f16x2 %0, %1, %2;" : "=r"(r.y) : "r"(x.y), "r"(y.y));
    asm("add.rn.f16x2 %0, %1, %2;" : "=r"(r.z) : "r"(x.z), "r"(y.z));
    asm("add.rn.f16x2 %0, %1, %2;" : "=r"(r.w) : "r"(x.w), "r"(y.w));
    return r;
}

// ---------------- CSR build ----------------
// 8 edges per thread: 8 independent atomics in flight
__global__ void k_deg(const int* __restrict__ ei, int E) {
    int t = blockIdx.x * blockDim.x + threadIdx.x;
    int i0 = t * 8;
    if (i0 + 7 < E) {
        int4 a = *(const int4*)(ei + E + i0);
        int4 b = *(const int4*)(ei + E + i0 + 4);
        atomicAdd(&g_deg[a.x], 1); atomicAdd(&g_deg[a.y], 1);
        atomicAdd(&g_deg[a.z], 1); atomicAdd(&g_deg[a.w], 1);
        atomicAdd(&g_deg[b.x], 1); atomicAdd(&g_deg[b.y], 1);
        atomicAdd(&g_deg[b.z], 1); atomicAdd(&g_deg[b.w], 1);
    } else {
        for (int i = i0; i < E; i++) atomicAdd(&g_deg[ei[E + i]], 1);
    }
}

// single-block coalesced scan over g_deg -> g_row (exclusive); g_cur, g_dinv.
// Self-restoring: writes g_deg back to 0; also zeroes g_pool and g_bn.
__global__ void k_scan() {
    __shared__ int wsum[32];
    int t = threadIdx.x, lane = t & 31, w = t >> 5;
    int carry = 0;
    for (int base = 0; base < Nn; base += 1024) {
        int idx = base + t;
        int v = (idx < Nn) ? g_deg[idx] : 0;
        int x = v;
#pragma unroll
        for (int off = 1; off < 32; off <<= 1) {
            int y = __shfl_up_sync(~0u, x, off);
            if (lane >= off) x += y;
        }
        if (lane == 31) wsum[w] = x;
        __syncthreads();
        if (w == 0) {
            int s = wsum[lane];
#pragma unroll
            for (int off = 1; off < 32; off <<= 1) {
                int y = __shfl_up_sync(~0u, s, off);
                if (lane >= off) s += y;
            }
            wsum[lane] = s;
        }
        __syncthreads();
        int woff = (w == 0) ? 0 : wsum[w - 1];
        int excl = carry + woff + x - v;
        if (idx < Nn) {
            g_row[idx] = excl;
            g_cur[idx] = excl;
            g_dinv[idx] = rsqrtf((float)(v + 1));  // +1 self loop
            g_deg[idx] = 0;                        // restore for next call
        }
        int tot = wsum[31];
        __syncthreads();
        carry += tot;
    }
    if (t == 0) g_row[Nn] = carry;
    // zero accumulators for this call
    for (int i = t; i < Gg * 16; i += 1024) g_pool[i] = 0.f;
    for (int i = t; i < 6 * 64; i += 1024) g_bn[i] = 0.f;
}

// Fused: CSR fill (8 edges/thread) + x conversion (x' = x*dinv -> 32 halfs padded)
__global__ void k_fillconvx(const int* __restrict__ ei, const float* __restrict__ x,
                            int E, int nt_fill) {
    int t = blockIdx.x * blockDim.x + threadIdx.x;
    if (t < nt_fill) {
        int i0 = t * 8;
        if (i0 + 7 < E) {
            int4 sa = *(const int4*)(ei + i0);
            int4 sb = *(const int4*)(ei + i0 + 4);
            int4 da = *(const int4*)(ei + E + i0);
            int4 db = *(const int4*)(ei + E + i0 + 4);
            int p0 = atomicAdd(&g_cur[da.x], 1);
            int p1 = atomicAdd(&g_cur[da.y], 1);
            int p2 = atomicAdd(&g_cur[da.z], 1);
            int p3 = atomicAdd(&g_cur[da.w], 1);
            int p4 = atomicAdd(&g_cur[db.x], 1);
            int p5 = atomicAdd(&g_cur[db.y], 1);
            int p6 = atomicAdd(&g_cur[db.z], 1);
            int p7 = atomicAdd(&g_cur[db.w], 1);
            g_csrc[p0] = sa.x; g_csrc[p1] = sa.y; g_csrc[p2] = sa.z; g_csrc[p3] = sa.w;
            g_csrc[p4] = sb.x; g_csrc[p5] = sb.y; g_csrc[p6] = sb.z; g_csrc[p7] = sb.w;
        } else {
            for (int i = i0; i < E; i++) {
                int p = atomicAdd(&g_cur[ei[E + i]], 1);
                g_csrc[p] = ei[i];
            }
        }
    } else {
        int tt = t - nt_fill;          // 0 .. Nn*4-1
        if (tt >= Nn * 4) return;
        int node = tt >> 2, q = tt & 3;
        float di = g_dinv[node];
        __half hv[8];
#pragma unroll
        for (int k = 0; k < 8; k++) {
            int c = q * 8 + k;
            float v = (c < 20) ? x[node * 20 + c] * di : 0.f;
            hv[k] = __float2half_rn(v);
        }
        g_xh[node * 4 + q] = *(const uint4*)hv;
    }
}

// ---------------- GCN CSR gather (half rows, dinv pre-folded, 2-stage pipeline) ----------------
template <int U4, bool STATS>
__global__ void k_gcn(const uint4* __restrict__ rows, const float* __restrict__ b,
                      float4* __restrict__ out4, float* __restrict__ stat) {
    const int F = U4 * 8;
    __shared__ float ss[F], sq[F];
    if (STATS) {
        if (threadIdx.x < F) { ss[threadIdx.x] = 0.f; sq[threadIdx.x] = 0.f; }
        __syncthreads();
    }
    const int GPW = 32 / U4;
    int lane = threadIdx.x & 31, warp = threadIdx.x >> 5;
    int grp = lane / U4, j = lane % U4;
    int node = (blockIdx.x * (blockDim.x >> 5) + warp) * GPW + grp;
    bool act = node < Nn;
    float a[8] = {0, 0, 0, 0, 0, 0, 0, 0};
    float di = 0.f;
    int r0 = 0, r1 = 0;
    if (act) {
        di = g_dinv[node];
        r0 = g_row[node];
        r1 = g_row[node + 1];
        acc8(a, __ldg(&rows[node * U4 + j]));  // self
    }
    int nb = (r1 - r0) >> 2;
    int k = r0 + (nb << 2);          // tail start
    if (nb >= 2) {
        int p0 = __ldg(&g_csrc[r0]),     p1 = __ldg(&g_csrc[r0 + 1]);
        int p2 = __ldg(&g_csrc[r0 + 2]), p3 = __ldg(&g_csrc[r0 + 3]);
        int q0 = __ldg(&g_csrc[r0 + 4]), q1 = __ldg(&g_csrc[r0 + 5]);
        int q2 = __ldg(&g_csrc[r0 + 6]), q3 = __ldg(&g_csrc[r0 + 7]);
        uint4 va0 = __ldg(&rows[p0 * U4 + j]);
        uint4 va1 = __ldg(&rows[p1 * U4 + j]);
        uint4 va2 = __ldg(&rows[p2 * U4 + j]);
        uint4 va3 = __ldg(&rows[p3 * U4 + j]);
        for (int t = 0; t < nb - 1; t++) {
            int c0, c1, c2, c3;
            bool more = (t + 2) < nb;
            if (more) {
                int base = r0 + (t + 2) * 4;
                c0 = __ldg(&g_csrc[base]);     c1 = __ldg(&g_csrc[base + 1]);
                c2 = __ldg(&g_csrc[base + 2]); c3 = __ldg(&g_csrc[base + 3]);
            }
            uint4 vb0 = __ldg(&rows[q0 * U4 + j]);
            uint4 vb1 = __ldg(&rows[q1 * U4 + j]);
            uint4 vb2 = __ldg(&rows[q2 * U4 + j]);
            uint4 vb3 = __ldg(&rows[q3 * U4 + j]);
            acc8(a, hadd4(va0, va1));
            acc8(a, hadd4(va2, va3));
            va0 = vb0; va1 = vb1; va2 = vb2; va3 = vb3;
            if (more) { q0 = c0; q1 = c1; q2 = c2; q3 = c3; }
        }
        acc8(a, hadd4(va0, va1));
        acc8(a, hadd4(va2, va3));
    } else if (nb == 1) {
        int p0 = __ldg(&g_csrc[r0]),     p1 = __ldg(&g_csrc[r0 + 1]);
        int p2 = __ldg(&g_csrc[r0 + 2]), p3 = __ldg(&g_csrc[r0 + 3]);
        uint4 va0 = __ldg(&rows[p0 * U4 + j]);
        uint4 va1 = __ldg(&rows[p1 * U4 + j]);
        uint4 va2 = __ldg(&rows[p2 * U4 + j]);
        uint4 va3 = __ldg(&rows[p3 * U4 + j]);
        acc8(a, hadd4(va0, va1));
        acc8(a, hadd4(va2, va3));
    }
    for (; k < r1; k++) acc8(a, __ldg(&rows[__ldg(&g_csrc[k]) * U4 + j]));

    float o[8];
    float4 b0 = b ? __ldg(&((const float4*)b)[j * 2])     : make_float4(0, 0, 0, 0);
    float4 b1 = b ? __ldg(&((const float4*)b)[j * 2 + 1]) : make_float4(0, 0, 0, 0);
#pragma unroll
    for (int c = 0; c < 8; c++) {
        float bb = (c < 4) ? (&b0.x)[c] : (&b1.x)[c - 4];
        o[c] = act ? (a[c] * di + bb) : 0.f;
    }
    if (act) {
        out4[node * (U4 * 2) + j * 2]     = make_float4(o[0], o[1], o[2], o[3]);
        out4[node * (U4 * 2) + j * 2 + 1] = make_float4(o[4], o[5], o[6], o[7]);
    }
    if (STATS) {
        float q[8];
#pragma unroll
        for (int c = 0; c < 8; c++) q[c] = o[c] * o[c];
#pragma unroll
        for (int off = U4; off < 32; off <<= 1) {
#pragma unroll
            for (int c = 0; c < 8; c++) {
                o[c] += __shfl_xor_sync(~0u, o[c], off);
                q[c] += __shfl_xor_sync(~0u, q[c], off);
            }
        }
        if (grp == 0) {
#pragma unroll
            for (int c = 0; c < 8; c++) {
                atomicAdd(&ss[j * 8 + c], o[c]);
                atomicAdd(&sq[j * 8 + c], q[c]);
            }
        }
        __syncthreads();
        if (threadIdx.x < F) {
            atomicAdd(&stat[threadIdx.x], ss[threadIdx.x]);
            atomicAdd(&stat[F + threadIdx.x], sq[threadIdx.x]);
        }
    }
}

// ---------------- GEMM layer 1: axp(20 of 32) @ W1 + b1 -> acc1, with stats ----------------
__global__ void k_gemm1(const float* __restrict__ h, const float* __restrict__ W,
                        const float* __restrict__ bias, float* __restrict__ out,
                        float* __restrict__ stat) {
    __shared__ float Ws[20 * 64];
    __shared__ float ss[64], sq[64];
    int tid = threadIdx.x;
    for (int i = tid; i < 20 * 64; i += 512) Ws[i] = W[i];
    if (tid < 64) { ss[tid] = 0.f; sq[tid] = 0.f; }
    __syncthreads();
    int fo = tid & 63, r = tid >> 6;
    int node = blockIdx.x * 8 + r;                 // 100000/8 = 12500 exact
    const float* hr = h + node * 32;
    float a = bias[fo];
#pragma unroll
    for (int fi = 0; fi < 20; fi++) a += hr[fi] * Ws[fi * 64 + fo];
    out[node * 64 + fo] = a;
    atomicAdd(&ss[fo], a);
    atomicAdd(&sq[fo], a * a);
    __syncthreads();
    if (tid < 64) {
        atomicAdd(&stat[tid], ss[tid]);
        atomicAdd(&stat[64 + tid], sq[tid]);
    }
}

// ---------------- fused BN+ReLU + GEMM + *dinv -> half ----------------
template <int FI, int FO>
__global__ void k_gemmbn(const float* __restrict__ acc, const float* __restrict__ stat,
                         const float* __restrict__ g, const float* __restrict__ be,
                         const float* __restrict__ W, __half* __restrict__ out) {
    const int BLK = 512;
    const int ROWS = BLK / FO;
    __shared__ float Ws[FI * FO];
    __shared__ float Hs[ROWS * FI];
    __shared__ float sc[FI], sh[FI];
    int tid = threadIdx.x;
    for (int i = tid; i < FI * FO; i += BLK) Ws[i] = W[i];
    if (tid < FI) {
        const float invn = 1.0f / (float)Nn;
        float mu  = stat[tid] * invn;
        float var = stat[FI + tid] * invn - mu * mu;
        float kk  = g[tid] * rsqrtf(var + BN_EPS);
        sc[tid] = kk;
        sh[tid] = be[tid] - mu * kk;
    }
    __syncthreads();
    int node0 = blockIdx.x * ROWS;
    for (int i = tid; i < ROWS * FI; i += BLK) {
        int r = i / FI, f = i % FI;
        Hs[i] = fmaxf(acc[(node0 + r) * FI + f] * sc[f] + sh[f], 0.f);
    }
    __syncthreads();
    int fo = tid % FO, r = tid / FO;
    int node = node0 + r;
    float a = 0.f;
#pragma unroll
    for (int fi = 0; fi < FI; fi++) a += Hs[r * FI + fi] * Ws[fi * FO + fo];
    a *= g_dinv[node];
    out[node * FO + fo] = __float2half_rn(a);
}

// was[k][h] = sum_c Wg[k][h*16+c]*att_src[h][c]; wad likewise. 128 threads.
__global__ void k_prep(const float* __restrict__ Wg, const float* __restrict__ asrc,
                       const float* __restrict__ adst) {
    int t = threadIdx.x;
    int k = t >> 3, h = t & 7;
    float s1 = 0.f, s2 = 0.f;
#pragma unroll
    for (int c = 0; c < 16; c++) {
        float w = Wg[k * 128 + h * 16 + c];
        s1 += w * asrc[h * 16 + c];
        s2 += w * adst[h * 16 + c];
    }
    g_was[k * 8 + h] = s1;
    g_wad[k * 8 + h] = s2;
}

// fused BN+ReLU(layer3) + h3->half + attention dots. block=256 -> 16 nodes. Nn%16==0.
__global__ void k_bn3att(const float* __restrict__ acc3, const float* __restrict__ stat,
                         const float* __restrict__ g, const float* __restrict__ be) {
    __shared__ float sv[16][17];
    __shared__ float sw[2][16][8];
    int t = threadIdx.x;
    if (t < 128) { sw[0][t >> 3][t & 7] = g_was[t]; sw[1][t >> 3][t & 7] = g_wad[t]; }
    int node0 = blockIdx.x * 16;
    int nl = t >> 4, f = t & 15;
    const float invn = 1.0f / (float)Nn;
    float mu  = stat[f] * invn;
    float var = stat[16 + f] * invn - mu * mu;
    float v = (acc3[(node0 + nl) * 16 + f] - mu) * rsqrtf(var + BN_EPS) * g[f] + be[f];
    v = fmaxf(v, 0.f);
    sv[nl][f] = v;
    __syncthreads();
    if (t < 64) {
        int n2 = t >> 2, q = t & 3;
        __half2 p0 = __floats2half2_rn(sv[n2][q * 4 + 0], sv[n2][q * 4 + 1]);
        __half2 p1 = __floats2half2_rn(sv[n2][q * 4 + 2], sv[n2][q * 4 + 3]);
        uint2 u;
        u.x = *(unsigned*)&p0;
        u.y = *(unsigned*)&p1;
        g_h3h[(node0 + n2) * 4 + q] = u;
    }
    if (t < 128) {
        int n3 = t >> 3, h = t & 7;
        float s1 = 0.f, s2 = 0.f;
#pragma unroll
        for (int k = 0; k < 16; k++) {
            float hv = sv[n3][k];
            s1 += hv * sw[0][k][h];
            s2 += hv * sw[1][k][h];
        }
        g_as[(node0 + n3) * 8 + h] = s1;
        g_ad[(node0 + n3) * 8 + h] = s2;
    }
}

// ---------------- fused GAT (no-max softmax: logits are small & sums all-positive) ----------------
__device__ __forceinline__ void gat_step(float l, uint2 u, float& sum, float4& acc) {
    float e = __expf(l);
    float2 f0 = __half22float2(*(const __half2*)&u.x);
    float2 f1 = __half22float2(*(const __half2*)&u.y);
    sum += e;
    acc.x += e * f0.x; acc.y += e * f0.y; acc.z += e * f1.x; acc.w += e * f1.y;
}

__global__ void k_gat(const float* __restrict__ Wg, const float* __restrict__ bg,
                      const int* __restrict__ batch) {
    __shared__ float Wgs[16 * 128];
    __shared__ float buf[8][8][16];     // [warp][head][k]
    for (int i = threadIdx.x; i < 16 * 128; i += blockDim.x) Wgs[i] = Wg[i];
    __syncthreads();
    int lane = threadIdx.x & 31, warp = threadIdx.x >> 5;
    int d = blockIdx.x * 8 + warp;      // grid = Nn/8 exact
    int h = lane >> 2, j = lane & 3;
    float adh = g_ad[d * 8 + h];
    int r0 = g_row[d], r1 = g_row[d + 1];

    // init with self edge
    float e0 = __expf(leaky(g_as[d * 8 + h] + adh));
    float sum = e0;
    uint2 su = __ldg(&g_h3h[d * 4 + j]);
    float2 sf0 = __half22float2(*(const __half2*)&su.x);
    float2 sf1 = __half22float2(*(const __half2*)&su.y);
    float4 acc = make_float4(e0 * sf0.x, e0 * sf0.y, e0 * sf1.x, e0 * sf1.y);

    int nb = (r1 - r0) >> 2;
    int k = r0 + (nb << 2);             // tail start
    if (nb >= 2) {
        int p0 = __ldg(&g_csrc[r0]),     p1 = __ldg(&g_csrc[r0 + 1]);
        int p2 = __ldg(&g_csrc[r0 + 2]), p3 = __ldg(&g_csrc[r0 + 3]);
        int q0 = __ldg(&g_csrc[r0 + 4]), q1 = __ldg(&g_csrc[r0 + 5]);
        int q2 = __ldg(&g_csrc[r0 + 6]), q3 = __ldg(&g_csrc[r0 + 7]);
        float la0 = __ldg(&g_as[p0 * 8 + h]), la1 = __ldg(&g_as[p1 * 8 + h]);
        float la2 = __ldg(&g_as[p2 * 8 + h]), la3 = __ldg(&g_as[p3 * 8 + h]);
        uint2 ua0 = __ldg(&g_h3h[p0 * 4 + j]);
        uint2 ua1 = __ldg(&g_h3h[p1 * 4 + j]);
        uint2 ua2 = __ldg(&g_h3h[p2 * 4 + j]);
        uint2 ua3 = __ldg(&g_h3h[p3 * 4 + j]);
        for (int t = 0; t < nb - 1; t++) {
            int c0, c1, c2, c3;
            bool more = (t + 2) < nb;
            if (more) {
                int base = r0 + (t + 2) * 4;
                c0 = __ldg(&g_csrc[base]);     c1 = __ldg(&g_csrc[base + 1]);
                c2 = __ldg(&g_csrc[base + 2]); c3 = __ldg(&g_csrc[base + 3]);
            }
            float lb0 = __ldg(&g_as[q0 * 8 + h]), lb1 = __ldg(&g_as[q1 * 8 + h]);
            float lb2 = __ldg(&g_as[q2 * 8 + h]), lb3 = __ldg(&g_as[q3 * 8 + h]);
            uint2 ub0 = __ldg(&g_h3h[q0 * 4 + j]);
            uint2 ub1 = __ldg(&g_h3h[q1 * 4 + j]);
            uint2 ub2 = __ldg(&g_h3h[q2 * 4 + j]);
            uint2 ub3 = __ldg(&g_h3h[q3 * 4 + j]);
            gat_step(leaky(la0 + adh), ua0, sum, acc);
            gat_step(leaky(la1 + adh), ua1, sum, acc);
            gat_step(leaky(la2 + adh), ua2, sum, acc);
            gat_step(leaky(la3 + adh), ua3, sum, acc);
            la0 = lb0; la1 = lb1; la2 = lb2; la3 = lb3;
            ua0 = ub0; ua1 = ub1; ua2 = ub2; ua3 = ub3;
            if (more) { q0 = c0; q1 = c1; q2 = c2; q3 = c3; }
        }
        gat_step(leaky(la0 + adh), ua0, sum, acc);
        gat_step(leaky(la1 + adh), ua1, sum, acc);
        gat_step(leaky(la2 + adh), ua2, sum, acc);
        gat_step(leaky(la3 + adh), ua3, sum, acc);
    } else if (nb == 1) {
        int p0 = __ldg(&g_csrc[r0]),     p1 = __ldg(&g_csrc[r0 + 1]);
        int p2 = __ldg(&g_csrc[r0 + 2]), p3 = __ldg(&g_csrc[r0 + 3]);
        float la0 = __ldg(&g_as[p0 * 8 + h]), la1 = __ldg(&g_as[p1 * 8 + h]);
        float la2 = __ldg(&g_as[p2 * 8 + h]), la3 = __ldg(&g_as[p3 * 8 + h]);
        uint2 ua0 = __ldg(&g_h3h[p0 * 4 + j]);
        uint2 ua1 = __ldg(&g_h3h[p1 * 4 + j]);
        uint2 ua2 = __ldg(&g_h3h[p2 * 4 + j]);
        uint2 ua3 = __ldg(&g_h3h[p3 * 4 + j]);
        gat_step(leaky(la0 + adh), ua0, sum, acc);
        gat_step(leaky(la1 + adh), ua1, sum, acc);
        gat_step(leaky(la2 + adh), ua2, sum, acc);
        gat_step(leaky(la3 + adh), ua3, sum, acc);
    }
    for (; k < r1; k++) {
        int s = __ldg(&g_csrc[k]);
        float l = leaky(__ldg(&g_as[s * 8 + h]) + adh);
        gat_step(l, __ldg(&g_h3h[s * 4 + j]), sum, acc);
    }
    float sc = 0.125f / sum;  // alpha-normalize + head-mean
    buf[warp][h][j * 4 + 0] = acc.x * sc;
    buf[warp][h][j * 4 + 1] = acc.y * sc;
    buf[warp][h][j * 4 + 2] = acc.z * sc;
    buf[warp][h][j * 4 + 3] = acc.w * sc;
    __syncwarp();

    // mini-GEMM: hg[c] = bg[c] + sum_h sum_k buf[h][k]*Wg[k][h*16+c]; then pool
    if (lane < 4) {
        float4 hg = ((const float4*)bg)[lane];
#pragma unroll
        for (int hh = 0; hh < 8; hh++) {
#pragma unroll
            for (int kk = 0; kk < 16; kk++) {
                float a = buf[warp][hh][kk];
                const float4 w = *(const float4*)&Wgs[kk * 128 + hh * 16 + lane * 4];
                hg.x += a * w.x; hg.y += a * w.y; hg.z += a * w.z; hg.w += a * w.w;
            }
        }
        red4(((float4*)g_pool) + batch[d] * 4 + lane, hg);
    }
}

__global__ void k_final(const float* __restrict__ Wf, const float* __restrict__ bf,
                        float* __restrict__ out) {
    int i = blockIdx.x * blockDim.x + threadIdx.x;
    if (i >= Gg * 3) return;
    int gg = i / 3, k = i % 3;
    float s = bf[k];
#pragma unroll
    for (int c = 0; c < 16; c++) s += g_pool[gg * 16 + c] * Wf[c * 3 + k];
    out[i] = s;
}

// ---------------- launch ----------------
static inline void* symaddr(const void* s) { void* p = nullptr; cudaGetSymbolAddress(&p, s); return p; }

extern "C" void kernel_launch(void* const* d_in, const int* in_sizes, int n_in,
                              void* d_out, int out_size) {
    const float* x       = (const float*)d_in[0];
    const int*   ei      = (const int*)  d_in[1];
    const int*   batch   = (const int*)  d_in[2];
    const float* W1 = (const float*)d_in[3],  *b1 = (const float*)d_in[4];
    const float* g1 = (const float*)d_in[5],  *be1= (const float*)d_in[6];
    const float* W2 = (const float*)d_in[7],  *b2 = (const float*)d_in[8];
    const float* g2 = (const float*)d_in[9],  *be2= (const float*)d_in[10];
    const float* W3 = (const float*)d_in[11], *b3 = (const float*)d_in[12];
    const float* g3 = (const float*)d_in[13], *be3= (const float*)d_in[14];
    const float* Wg = (const float*)d_in[15];
    const float* att_src = (const float*)d_in[16];
    const float* att_dst = (const float*)d_in[17];
    const float* bg = (const float*)d_in[18];
    const float* Wf = (const float*)d_in[19], *bf = (const float*)d_in[20];
    float* out = (float*)d_out;
    const int E = in_sizes[1] / 2;

    float* axp  = (float*)symaddr(g_axp);
    float* acc1 = (float*)symaddr(g_acc1);
    float* acc2 = (float*)symaddr(g_acc2);
    float* acc3 = (float*)symaddr(g_acc3);
    float* bn   = (float*)symaddr(g_bn);
    uint4* xh   = (uint4*)symaddr(g_xh);
    uint4* t2h  = (uint4*)symaddr(g_t2h);
    uint4* t3h  = (uint4*)symaddr(g_t3h);

    const int B = 256;
    // ---- CSR build (launch #1..#3) ----
    k_deg<<<(E / 8 + B) / B, B>>>(ei, E);
    k_scan<<<1, 1024>>>();
    int nt_fill = (E + 7) / 8;
    int nt_tot  = nt_fill + Nn * 4;
    k_fillconvx<<<(nt_tot + B - 1) / B, B>>>(ei, x, E, nt_fill);

    // ---- GCN layer 1 (launch #4 = profiled slot): aggregate x' (half), GEMM 20->64 (+stats) ----
    k_gcn<4, false><<<(Nn + 63) / 64, B>>>(xh, nullptr, (float4*)axp, nullptr);
    k_gemm1<<<Nn / 8, 512>>>(axp, W1, b1, acc1, bn + 0);

    // ---- GCN layer 2: fused BN1+ReLU+GEMM 64->32 (*dinv, half), aggregate (+stats) ----
    k_gemmbn<64, 32><<<Nn / 16, 512>>>(acc1, bn + 0, g1, be1, W2, (__half*)t2h);
    k_gcn<4, true><<<(Nn + 63) / 64, B>>>(t2h, b2, (float4*)acc2, bn + 128);

    // ---- GCN layer 3: fused BN2+ReLU+GEMM 32->16 (*dinv, half), aggregate (+stats) ----
    k_gemmbn<32, 16><<<Nn / 32, 512>>>(acc2, bn + 128, g2, be2, W3, (__half*)t3h);
    k_gcn<2, true><<<(Nn + 127) / 128, B>>>(t3h, b3, (float4*)acc3, bn + 256);

    // ---- BN3 + attention dots fused, then no-max GAT ----
    k_prep<<<1, 128>>>(Wg, att_src, att_dst);
    k_bn3att<<<Nn / 16, B>>>(acc3, bn + 256, g3, be3);
    k_gat<<<Nn / 8, B>>>(Wg, bg, batch);

    // ---- classifier ----
    k_final<<<(Gg * 3 + B - 1) / B, B>>>(Wf, bf, out);
}

// round 13
// speedup vs baseline: 1.1474x; 1.1474x over previous
#include <cuda_runtime.h>
#include <cuda_fp16.h>

#define Nn 100000
#define MAXE 3200000
#define Gg 5000
#define BUCKET 96
#define BN_EPS 1e-5f

// ---------------- scratch (static device globals; zero-initialized at load) ----------------
__device__ int      g_deg [Nn];          // reset by k_gat epilogue each call
__device__ int      g_csrc[Nn * BUCKET]; // bucketed adjacency (src lists per dst)
__device__ float    g_dinv[Nn];
__device__ uint4    g_xh  [Nn * 4];     // x' = x*dinv, padded to 32 halfs
__device__ float    g_axp [Nn * 32];    // aggregated x', padded 32 floats
__device__ uint4    g_t2h [Nn * 4];     // t2' = bnrelu(acc1)@W2*dinv, 32 halfs
__device__ uint4    g_t3h [Nn * 2];     // t3' = bnrelu(acc2)@W3*dinv, 16 halfs
__device__ uint2    g_h3h [Nn * 4];     // h3 post-BN, 16 halfs
__device__ float    g_acc1[Nn * 64];
__device__ float    g_acc2[Nn * 32];
__device__ float    g_acc3[Nn * 16];
__device__ float    g_as  [Nn * 8];
__device__ float    g_ad  [Nn * 8];
__device__ float    g_was [16 * 8];
__device__ float    g_wad [16 * 8];
__device__ float    g_pool[Gg * 16];    // reset by k_final after reading
__device__ float    g_bn  [6 * 64];     // zeroed by k_fillb block 0 each call (strided loop!)

// ---------------- helpers ----------------
__device__ __forceinline__ void red4(float4* p, float4 v) {
    asm volatile("red.global.add.v4.f32 [%0], {%1,%2,%3,%4};"
                 :: "l"(p), "f"(v.x), "f"(v.y), "f"(v.z), "f"(v.w) : "memory");
}
__device__ __forceinline__ float leaky(float v) { return v > 0.f ? v : 0.2f * v; }
__device__ __forceinline__ void acc8(float* a, uint4 u) {
    const __half2* h = (const __half2*)&u;
    float2 f0 = __half22float2(h[0]); a[0] += f0.x; a[1] += f0.y;
    float2 f1 = __half22float2(h[1]); a[2] += f1.x; a[3] += f1.y;
    float2 f2 = __half22float2(h[2]); a[4] += f2.x; a[5] += f2.y;
    float2 f3 = __half22float2(h[3]); a[6] += f3.x; a[7] += f3.y;
}
// packed fp16 pairwise add (one HADD2 per half2 lane)
__device__ __forceinline__ uint4 hadd4(uint4 x, uint4 y) {
    uint4 r;
    asm("add.rn.f16x2 %0, %1, %2;" : "=r"(r.x) : "r"(x.x), "r"(y.x));
    asm("add.rn.f16x2 %0, %1, %2;" : "=r"(r.y) : "r"(x.y), "r"(y.y));
    asm("add.rn.f16x2 %0, %1, %2;" : "=r"(r.z) : "r"(x.z), "r"(y.z));
    asm("add.rn.f16x2 %0, %1, %2;" : "=r"(r.w) : "r"(x.w), "r"(y.w));
    return r;
}

// ---------------- single-pass bucket build (no prefix sum needed) ----------------
// 8 edges/thread. Block 0 also zeroes g_bn for this call (strided: covers all 384).
__global__ void k_fillb(const int* __restrict__ ei, int E) {
    if (blockIdx.x == 0) {
        for (int i = threadIdx.x; i < 6 * 64; i += blockDim.x) g_bn[i] = 0.f;
    }
    int t = blockIdx.x * blockDim.x + threadIdx.x;
    int i0 = t * 8;
    if (i0 + 7 < E) {
        int4 sa = *(const int4*)(ei + i0);
        int4 sb = *(const int4*)(ei + i0 + 4);
        int4 da = *(const int4*)(ei + E + i0);
        int4 db = *(const int4*)(ei + E + i0 + 4);
        int p0 = atomicAdd(&g_deg[da.x], 1);
        int p1 = atomicAdd(&g_deg[da.y], 1);
        int p2 = atomicAdd(&g_deg[da.z], 1);
        int p3 = atomicAdd(&g_deg[da.w], 1);
        int p4 = atomicAdd(&g_deg[db.x], 1);
        int p5 = atomicAdd(&g_deg[db.y], 1);
        int p6 = atomicAdd(&g_deg[db.z], 1);
        int p7 = atomicAdd(&g_deg[db.w], 1);
        g_csrc[da.x * BUCKET + p0] = sa.x;
        g_csrc[da.y * BUCKET + p1] = sa.y;
        g_csrc[da.z * BUCKET + p2] = sa.z;
        g_csrc[da.w * BUCKET + p3] = sa.w;
        g_csrc[db.x * BUCKET + p4] = sb.x;
        g_csrc[db.y * BUCKET + p5] = sb.y;
        g_csrc[db.z * BUCKET + p6] = sb.z;
        g_csrc[db.w * BUCKET + p7] = sb.w;
    } else {
        for (int i = i0; i < E; i++) {
            int d = ei[E + i];
            int p = atomicAdd(&g_deg[d], 1);
            g_csrc[d * BUCKET + p] = ei[i];
        }
    }
}

// dinv from deg + x' = x*dinv -> 32 halfs padded. Nn*4 threads.
__global__ void k_dinvconvx(const float* __restrict__ x) {
    int t = blockIdx.x * blockDim.x + threadIdx.x;
    if (t >= Nn * 4) return;
    int node = t >> 2, q = t & 3;
    float di = rsqrtf((float)(g_deg[node] + 1));   // +1 self loop
    if (q == 0) g_dinv[node] = di;
    __half hv[8];
#pragma unroll
    for (int k = 0; k < 8; k++) {
        int c = q * 8 + k;
        float v = (c < 20) ? x[node * 20 + c] * di : 0.f;
        hv[k] = __float2half_rn(v);
    }
    g_xh[node * 4 + q] = *(const uint4*)hv;
}

// ---------------- GCN bucket gather (half rows, dinv pre-folded, 2-stage pipeline) ----------------
template <int U4, bool STATS>
__global__ void k_gcn(const uint4* __restrict__ rows, const float* __restrict__ b,
                      float4* __restrict__ out4, float* __restrict__ stat) {
    const int F = U4 * 8;
    __shared__ float ss[F], sq[F];
    if (STATS) {
        if (threadIdx.x < F) { ss[threadIdx.x] = 0.f; sq[threadIdx.x] = 0.f; }
        __syncthreads();
    }
    const int GPW = 32 / U4;
    int lane = threadIdx.x & 31, warp = threadIdx.x >> 5;
    int grp = lane / U4, j = lane % U4;
    int node = (blockIdx.x * (blockDim.x >> 5) + warp) * GPW + grp;
    bool act = node < Nn;
    float a[8] = {0, 0, 0, 0, 0, 0, 0, 0};
    float di = 0.f;
    int r0 = 0, r1 = 0;
    if (act) {
        di = g_dinv[node];
        r0 = node * BUCKET;
        r1 = r0 + g_deg[node];
        acc8(a, __ldg(&rows[node * U4 + j]));  // self
    }
    int nb = (r1 - r0) >> 2;
    int k = r0 + (nb << 2);          // tail start
    if (nb >= 2) {
        int p0 = __ldg(&g_csrc[r0]),     p1 = __ldg(&g_csrc[r0 + 1]);
        int p2 = __ldg(&g_csrc[r0 + 2]), p3 = __ldg(&g_csrc[r0 + 3]);
        int q0 = __ldg(&g_csrc[r0 + 4]), q1 = __ldg(&g_csrc[r0 + 5]);
        int q2 = __ldg(&g_csrc[r0 + 6]), q3 = __ldg(&g_csrc[r0 + 7]);
        uint4 va0 = __ldg(&rows[p0 * U4 + j]);
        uint4 va1 = __ldg(&rows[p1 * U4 + j]);
        uint4 va2 = __ldg(&rows[p2 * U4 + j]);
        uint4 va3 = __ldg(&rows[p3 * U4 + j]);
        for (int t = 0; t < nb - 1; t++) {
            int c0, c1, c2, c3;
            bool more = (t + 2) < nb;
            if (more) {
                int base = r0 + (t + 2) * 4;
                c0 = __ldg(&g_csrc[base]);     c1 = __ldg(&g_csrc[base + 1]);
                c2 = __ldg(&g_csrc[base + 2]); c3 = __ldg(&g_csrc[base + 3]);
            }
            uint4 vb0 = __ldg(&rows[q0 * U4 + j]);
            uint4 vb1 = __ldg(&rows[q1 * U4 + j]);
            uint4 vb2 = __ldg(&rows[q2 * U4 + j]);
            uint4 vb3 = __ldg(&rows[q3 * U4 + j]);
            acc8(a, hadd4(va0, va1));
            acc8(a, hadd4(va2, va3));
            va0 = vb0; va1 = vb1; va2 = vb2; va3 = vb3;
            if (more) { q0 = c0; q1 = c1; q2 = c2; q3 = c3; }
        }
        acc8(a, hadd4(va0, va1));
        acc8(a, hadd4(va2, va3));
    } else if (nb == 1) {
        int p0 = __ldg(&g_csrc[r0]),     p1 = __ldg(&g_csrc[r0 + 1]);
        int p2 = __ldg(&g_csrc[r0 + 2]), p3 = __ldg(&g_csrc[r0 + 3]);
        uint4 va0 = __ldg(&rows[p0 * U4 + j]);
        uint4 va1 = __ldg(&rows[p1 * U4 + j]);
        uint4 va2 = __ldg(&rows[p2 * U4 + j]);
        uint4 va3 = __ldg(&rows[p3 * U4 + j]);
        acc8(a, hadd4(va0, va1));
        acc8(a, hadd4(va2, va3));
    }
    for (; k < r1; k++) acc8(a, __ldg(&rows[__ldg(&g_csrc[k]) * U4 + j]));

    float o[8];
    float4 b0 = b ? __ldg(&((const float4*)b)[j * 2])     : make_float4(0, 0, 0, 0);
    float4 b1 = b ? __ldg(&((const float4*)b)[j * 2 + 1]) : make_float4(0, 0, 0, 0);
#pragma unroll
    for (int c = 0; c < 8; c++) {
        float bb = (c < 4) ? (&b0.x)[c] : (&b1.x)[c - 4];
        o[c] = act ? (a[c] * di + bb) : 0.f;
    }
    if (act) {
        out4[node * (U4 * 2) + j * 2]     = make_float4(o[0], o[1], o[2], o[3]);
        out4[node * (U4 * 2) + j * 2 + 1] = make_float4(o[4], o[5], o[6], o[7]);
    }
    if (STATS) {
        float q[8];
#pragma unroll
        for (int c = 0; c < 8; c++) q[c] = o[c] * o[c];
#pragma unroll
        for (int off = U4; off < 32; off <<= 1) {
#pragma unroll
            for (int c = 0; c < 8; c++) {
                o[c] += __shfl_xor_sync(~0u, o[c], off);
                q[c] += __shfl_xor_sync(~0u, q[c], off);
            }
        }
        if (grp == 0) {
#pragma unroll
            for (int c = 0; c < 8; c++) {
                atomicAdd(&ss[j * 8 + c], o[c]);
                atomicAdd(&sq[j * 8 + c], q[c]);
            }
        }
        __syncthreads();
        if (threadIdx.x < F) {
            atomicAdd(&stat[threadIdx.x], ss[threadIdx.x]);
            atomicAdd(&stat[F + threadIdx.x], sq[threadIdx.x]);
        }
    }
}

// ---------------- GEMM layer 1: axp(20 of 32) @ W1 + b1 -> acc1, with stats ----------------
__global__ void k_gemm1(const float* __restrict__ h, const float* __restrict__ W,
                        const float* __restrict__ bias, float* __restrict__ out,
                        float* __restrict__ stat) {
    __shared__ float Ws[20 * 64];
    __shared__ float ss[64], sq[64];
    int tid = threadIdx.x;
    for (int i = tid; i < 20 * 64; i += 512) Ws[i] = W[i];
    if (tid < 64) { ss[tid] = 0.f; sq[tid] = 0.f; }
    __syncthreads();
    int fo = tid & 63, r = tid >> 6;
    int node = blockIdx.x * 8 + r;                 // 100000/8 = 12500 exact
    const float* hr = h + node * 32;
    float a = bias[fo];
#pragma unroll
    for (int fi = 0; fi < 20; fi++) a += hr[fi] * Ws[fi * 64 + fo];
    out[node * 64 + fo] = a;
    atomicAdd(&ss[fo], a);
    atomicAdd(&sq[fo], a * a);
    __syncthreads();
    if (tid < 64) {
        atomicAdd(&stat[tid], ss[tid]);
        atomicAdd(&stat[64 + tid], sq[tid]);
    }
}

// ---------------- fused BN+ReLU + GEMM + *dinv -> half ----------------
template <int FI, int FO>
__global__ void k_gemmbn(const float* __restrict__ acc, const float* __restrict__ stat,
                         const float* __restrict__ g, const float* __restrict__ be,
                         const float* __restrict__ W, __half* __restrict__ out) {
    const int BLK = 512;
    const int ROWS = BLK / FO;
    __shared__ float Ws[FI * FO];
    __shared__ float Hs[ROWS * FI];
    __shared__ float sc[FI], sh[FI];
    int tid = threadIdx.x;
    for (int i = tid; i < FI * FO; i += BLK) Ws[i] = W[i];
    if (tid < FI) {
        const float invn = 1.0f / (float)Nn;
        float mu  = stat[tid] * invn;
        float var = stat[FI + tid] * invn - mu * mu;
        float kk  = g[tid] * rsqrtf(var + BN_EPS);
        sc[tid] = kk;
        sh[tid] = be[tid] - mu * kk;
    }
    __syncthreads();
    int node0 = blockIdx.x * ROWS;
    for (int i = tid; i < ROWS * FI; i += BLK) {
        int r = i / FI, f = i % FI;
        Hs[i] = fmaxf(acc[(node0 + r) * FI + f] * sc[f] + sh[f], 0.f);
    }
    __syncthreads();
    int fo = tid % FO, r = tid / FO;
    int node = node0 + r;
    float a = 0.f;
#pragma unroll
    for (int fi = 0; fi < FI; fi++) a += Hs[r * FI + fi] * Ws[fi * FO + fo];
    a *= g_dinv[node];
    out[node * FO + fo] = __float2half_rn(a);
}

// was[k][h] = sum_c Wg[k][h*16+c]*att_src[h][c]; wad likewise. 128 threads.
__global__ void k_prep(const float* __restrict__ Wg, const float* __restrict__ asrc,
                       const float* __restrict__ adst) {
    int t = threadIdx.x;
    int k = t >> 3, h = t & 7;
    float s1 = 0.f, s2 = 0.f;
#pragma unroll
    for (int c = 0; c < 16; c++) {
        float w = Wg[k * 128 + h * 16 + c];
        s1 += w * asrc[h * 16 + c];
        s2 += w * adst[h * 16 + c];
    }
    g_was[k * 8 + h] = s1;
    g_wad[k * 8 + h] = s2;
}

// fused BN+ReLU(layer3) + h3->half + attention dots. block=256 -> 16 nodes. Nn%16==0.
__global__ void k_bn3att(const float* __restrict__ acc3, const float* __restrict__ stat,
                         const float* __restrict__ g, const float* __restrict__ be) {
    __shared__ float sv[16][17];
    __shared__ float sw[2][16][8];
    int t = threadIdx.x;
    if (t < 128) { sw[0][t >> 3][t & 7] = g_was[t]; sw[1][t >> 3][t & 7] = g_wad[t]; }
    int node0 = blockIdx.x * 16;
    int nl = t >> 4, f = t & 15;
    const float invn = 1.0f / (float)Nn;
    float mu  = stat[f] * invn;
    float var = stat[16 + f] * invn - mu * mu;
    float v = (acc3[(node0 + nl) * 16 + f] - mu) * rsqrtf(var + BN_EPS) * g[f] + be[f];
    v = fmaxf(v, 0.f);
    sv[nl][f] = v;
    __syncthreads();
    if (t < 64) {
        int n2 = t >> 2, q = t & 3;
        __half2 p0 = __floats2half2_rn(sv[n2][q * 4 + 0], sv[n2][q * 4 + 1]);
        __half2 p1 = __floats2half2_rn(sv[n2][q * 4 + 2], sv[n2][q * 4 + 3]);
        uint2 u;
        u.x = *(unsigned*)&p0;
        u.y = *(unsigned*)&p1;
        g_h3h[(node0 + n2) * 4 + q] = u;
    }
    if (t < 128) {
        int n3 = t >> 3, h = t & 7;
        float s1 = 0.f, s2 = 0.f;
#pragma unroll
        for (int k = 0; k < 16; k++) {
            float hv = sv[n3][k];
            s1 += hv * sw[0][k][h];
            s2 += hv * sw[1][k][h];
        }
        g_as[(node0 + n3) * 8 + h] = s1;
        g_ad[(node0 + n3) * 8 + h] = s2;
    }
}

// ---------------- fused GAT (no-max softmax) + deg reset epilogue ----------------
__device__ __forceinline__ void gat_step(float l, uint2 u, float& sum, float4& acc) {
    float e = __expf(l);
    float2 f0 = __half22float2(*(const __half2*)&u.x);
    float2 f1 = __half22float2(*(const __half2*)&u.y);
    sum += e;
    acc.x += e * f0.x; acc.y += e * f0.y; acc.z += e * f1.x; acc.w += e * f1.y;
}

__global__ void k_gat(const float* __restrict__ Wg, const float* __restrict__ bg,
                      const int* __restrict__ batch) {
    __shared__ float Wgs[16 * 128];
    __shared__ float buf[8][8][16];     // [warp][head][k]
    for (int i = threadIdx.x; i < 16 * 128; i += blockDim.x) Wgs[i] = Wg[i];
    __syncthreads();
    int lane = threadIdx.x & 31, warp = threadIdx.x >> 5;
    int d = blockIdx.x * 8 + warp;      // grid = Nn/8 exact
    int h = lane >> 2, j = lane & 3;
    float adh = g_ad[d * 8 + h];
    int r0 = d * BUCKET, r1 = r0 + g_deg[d];

    // init with self edge
    float e0 = __expf(leaky(g_as[d * 8 + h] + adh));
    float sum = e0;
    uint2 su = __ldg(&g_h3h[d * 4 + j]);
    float2 sf0 = __half22float2(*(const __half2*)&su.x);
    float2 sf1 = __half22float2(*(const __half2*)&su.y);
    float4 acc = make_float4(e0 * sf0.x, e0 * sf0.y, e0 * sf1.x, e0 * sf1.y);

    int nb = (r1 - r0) >> 2;
    int k = r0 + (nb << 2);             // tail start
    if (nb >= 2) {
        int p0 = __ldg(&g_csrc[r0]),     p1 = __ldg(&g_csrc[r0 + 1]);
        int p2 = __ldg(&g_csrc[r0 + 2]), p3 = __ldg(&g_csrc[r0 + 3]);
        int q0 = __ldg(&g_csrc[r0 + 4]), q1 = __ldg(&g_csrc[r0 + 5]);
        int q2 = __ldg(&g_csrc[r0 + 6]), q3 = __ldg(&g_csrc[r0 + 7]);
        float la0 = __ldg(&g_as[p0 * 8 + h]), la1 = __ldg(&g_as[p1 * 8 + h]);
        float la2 = __ldg(&g_as[p2 * 8 + h]), la3 = __ldg(&g_as[p3 * 8 + h]);
        uint2 ua0 = __ldg(&g_h3h[p0 * 4 + j]);
        uint2 ua1 = __ldg(&g_h3h[p1 * 4 + j]);
        uint2 ua2 = __ldg(&g_h3h[p2 * 4 + j]);
        uint2 ua3 = __ldg(&g_h3h[p3 * 4 + j]);
        for (int t = 0; t < nb - 1; t++) {
            int c0, c1, c2, c3;
            bool more = (t + 2) < nb;
            if (more) {
                int base = r0 + (t + 2) * 4;
                c0 = __ldg(&g_csrc[base]);     c1 = __ldg(&g_csrc[base + 1]);
                c2 = __ldg(&g_csrc[base + 2]); c3 = __ldg(&g_csrc[base + 3]);
            }
            float lb0 = __ldg(&g_as[q0 * 8 + h]), lb1 = __ldg(&g_as[q1 * 8 + h]);
            float lb2 = __ldg(&g_as[q2 * 8 + h]), lb3 = __ldg(&g_as[q3 * 8 + h]);
            uint2 ub0 = __ldg(&g_h3h[q0 * 4 + j]);
            uint2 ub1 = __ldg(&g_h3h[q1 * 4 + j]);
            uint2 ub2 = __ldg(&g_h3h[q2 * 4 + j]);
            uint2 ub3 = __ldg(&g_h3h[q3 * 4 + j]);
            gat_step(leaky(la0 + adh), ua0, sum, acc);
            gat_step(leaky(la1 + adh), ua1, sum, acc);
            gat_step(leaky(la2 + adh), ua2, sum, acc);
            gat_step(leaky(la3 + adh), ua3, sum, acc);
            la0 = lb0; la1 = lb1; la2 = lb2; la3 = lb3;
            ua0 = ub0; ua1 = ub1; ua2 = ub2; ua3 = ub3;
            if (more) { q0 = c0; q1 = c1; q2 = c2; q3 = c3; }
        }
        gat_step(leaky(la0 + adh), ua0, sum, acc);
        gat_step(leaky(la1 + adh), ua1, sum, acc);
        gat_step(leaky(la2 + adh), ua2, sum, acc);
        gat_step(leaky(la3 + adh), ua3, sum, acc);
    } else if (nb == 1) {
        int p0 = __ldg(&g_csrc[r0]),     p1 = __ldg(&g_csrc[r0 + 1]);
        int p2 = __ldg(&g_csrc[r0 + 2]), p3 = __ldg(&g_csrc[r0 + 3]);
        float la0 = __ldg(&g_as[p0 * 8 + h]), la1 = __ldg(&g_as[p1 * 8 + h]);
        float la2 = __ldg(&g_as[p2 * 8 + h]), la3 = __ldg(&g_as[p3 * 8 + h]);
        uint2 ua0 = __ldg(&g_h3h[p0 * 4 + j]);
        uint2 ua1 = __ldg(&g_h3h[p1 * 4 + j]);
        uint2 ua2 = __ldg(&g_h3h[p2 * 4 + j]);
        uint2 ua3 = __ldg(&g_h3h[p3 * 4 + j]);
        gat_step(leaky(la0 + adh), ua0, sum, acc);
        gat_step(leaky(la1 + adh), ua1, sum, acc);
        gat_step(leaky(la2 + adh), ua2, sum, acc);
        gat_step(leaky(la3 + adh), ua3, sum, acc);
    }
    for (; k < r1; k++) {
        int s = __ldg(&g_csrc[k]);
        float l = leaky(__ldg(&g_as[s * 8 + h]) + adh);
        gat_step(l, __ldg(&g_h3h[s * 4 + j]), sum, acc);
    }
    float sc = 0.125f / sum;  // alpha-normalize + head-mean
    buf[warp][h][j * 4 + 0] = acc.x * sc;
    buf[warp][h][j * 4 + 1] = acc.y * sc;
    buf[warp][h][j * 4 + 2] = acc.z * sc;
    buf[warp][h][j * 4 + 3] = acc.w * sc;
    __syncwarp();

    // reset deg for the next call (this warp is the last reader of g_deg[d])
    if (lane == 0) g_deg[d] = 0;

    // mini-GEMM: hg[c] = bg[c] + sum_h sum_k buf[h][k]*Wg[k][h*16+c]; then pool
    if (lane < 4) {
        float4 hg = ((const float4*)bg)[lane];
#pragma unroll
        for (int hh = 0; hh < 8; hh++) {
#pragma unroll
            for (int kk = 0; kk < 16; kk++) {
                float a = buf[warp][hh][kk];
                const float4 w = *(const float4*)&Wgs[kk * 128 + hh * 16 + lane * 4];
                hg.x += a * w.x; hg.y += a * w.y; hg.z += a * w.z; hg.w += a * w.w;
            }
        }
        red4(((float4*)g_pool) + batch[d] * 4 + lane, hg);
    }
}

// one thread per graph: out[g] = pool[g]@Wf + bf, then zero its pool entries
__global__ void k_final(const float* __restrict__ Wf, const float* __restrict__ bf,
                        float* __restrict__ out) {
    int gg = blockIdx.x * blockDim.x + threadIdx.x;
    if (gg >= Gg) return;
    float p[16];
    float4* pp = (float4*)&g_pool[gg * 16];
#pragma unroll
    for (int q = 0; q < 4; q++) {
        float4 v = pp[q];
        p[q * 4 + 0] = v.x; p[q * 4 + 1] = v.y; p[q * 4 + 2] = v.z; p[q * 4 + 3] = v.w;
        pp[q] = make_float4(0.f, 0.f, 0.f, 0.f);   // reset for next call
    }
#pragma unroll
    for (int k = 0; k < 3; k++) {
        float s = bf[k];
#pragma unroll
        for (int c = 0; c < 16; c++) s += p[c] * Wf[c * 3 + k];
        out[gg * 3 + k] = s;
    }
}

// ---------------- launch ----------------
static inline void* symaddr(const void* s) { void* p = nullptr; cudaGetSymbolAddress(&p, s); return p; }

extern "C" void kernel_launch(void* const* d_in, const int* in_sizes, int n_in,
                              void* d_out, int out_size) {
    const float* x       = (const float*)d_in[0];
    const int*   ei      = (const int*)  d_in[1];
    const int*   batch   = (const int*)  d_in[2];
    const float* W1 = (const float*)d_in[3],  *b1 = (const float*)d_in[4];
    const float* g1 = (const float*)d_in[5],  *be1= (const float*)d_in[6];
    const float* W2 = (const float*)d_in[7],  *b2 = (const float*)d_in[8];
    const float* g2 = (const float*)d_in[9],  *be2= (const float*)d_in[10];
    const float* W3 = (const float*)d_in[11], *b3 = (const float*)d_in[12];
    const float* g3 = (const float*)d_in[13], *be3= (const float*)d_in[14];
    const float* Wg = (const float*)d_in[15];
    const float* att_src = (const float*)d_in[16];
    const float* att_dst = (const float*)d_in[17];
    const float* bg = (const float*)d_in[18];
    const float* Wf = (const float*)d_in[19], *bf = (const float*)d_in[20];
    float* out = (float*)d_out;
    const int E = in_sizes[1] / 2;

    float* axp  = (float*)symaddr(g_axp);
    float* acc1 = (float*)symaddr(g_acc1);
    float* acc2 = (float*)symaddr(g_acc2);
    float* acc3 = (float*)symaddr(g_acc3);
    float* bn   = (float*)symaddr(g_bn);
    uint4* xh   = (uint4*)symaddr(g_xh);
    uint4* t2h  = (uint4*)symaddr(g_t2h);
    uint4* t3h  = (uint4*)symaddr(g_t3h);

    const int B = 256;
    // ---- bucket adjacency build (single atomic pass; no prefix sum) ----
    k_fillb<<<(E / 8 + B) / B, B>>>(ei, E);
    k_dinvconvx<<<(Nn * 4 + B - 1) / B, B>>>(x);

    // ---- GCN layer 1: aggregate x' (half), GEMM 20->64 (+stats) ----
    k_gcn<4, false><<<(Nn + 63) / 64, B>>>(xh, nullptr, (float4*)axp, nullptr);
    k_gemm1<<<Nn / 8, 512>>>(axp, W1, b1, acc1, bn + 0);

    // ---- GCN layer 2: fused BN1+ReLU+GEMM 64->32 (*dinv, half), aggregate (+stats) ----
    k_gemmbn<64, 32><<<Nn / 16, 512>>>(acc1, bn + 0, g1, be1, W2, (__half*)t2h);
    k_gcn<4, true><<<(Nn + 63) / 64, B>>>(t2h, b2, (float4*)acc2, bn + 128);

    // ---- GCN layer 3: fused BN2+ReLU+GEMM 32->16 (*dinv, half), aggregate (+stats) ----
    k_gemmbn<32, 16><<<Nn / 32, 512>>>(acc2, bn + 128, g2, be2, W3, (__half*)t3h);
    k_gcn<2, true><<<(Nn + 127) / 128, B>>>(t3h, b3, (float4*)acc3, bn + 256);

    // ---- BN3 + attention dots fused, then no-max GAT (+deg reset) ----
    k_prep<<<1, 128>>>(Wg, att_src, att_dst);
    k_bn3att<<<Nn / 16, B>>>(acc3, bn + 256, g3, be3);
    k_gat<<<Nn / 8, B>>>(Wg, bg, batch);

    // ---- classifier (+pool reset) ----
    k_final<<<(Gg + B - 1) / B, B>>>(Wf, bf, out);
}

// round 14
// speedup vs baseline: 1.2481x; 1.0878x over previous
#include <cuda_runtime.h>
#include <cuda_fp16.h>

#define Nn 100000
#define MAXE 3200000
#define Gg 5000
#define BUCKET 96
#define BN_EPS 1e-5f

// ---------------- scratch (static device globals; zero-initialized at load) ----------------
__device__ int      g_deg [Nn];          // reset by k_gat epilogue each call
__device__ int      g_csrc[Nn * BUCKET]; // bucketed adjacency (src lists per dst)
__device__ float    g_dinv[Nn];
__device__ uint4    g_xh  [Nn * 4];     // x' = x*dinv, padded to 32 halfs
__device__ float    g_axp [Nn * 32];    // aggregated x', padded 32 floats
__device__ uint4    g_t2h [Nn * 4];     // t2' = bnrelu(acc1)@W2*dinv, 32 halfs
__device__ uint4    g_t3h [Nn * 2];     // t3' = bnrelu(acc2)@W3*dinv, 16 halfs
__device__ uint2    g_h3h [Nn * 4];     // h3 post-BN, 16 halfs
__device__ float    g_acc1[Nn * 64];
__device__ float    g_acc2[Nn * 32];
__device__ float    g_acc3[Nn * 16];
__device__ float    g_as  [Nn * 8];
__device__ float    g_ad  [Nn * 8];
__device__ float    g_was [16 * 8];
__device__ float    g_wad [16 * 8];
__device__ float    g_pool[Gg * 16];    // reset by k_final after reading
__device__ float    g_bn  [6 * 64];     // zeroed by k_fillb block 0 each call

// ---------------- helpers ----------------
__device__ __forceinline__ void red4(float4* p, float4 v) {
    asm volatile("red.global.add.v4.f32 [%0], {%1,%2,%3,%4};"
                 :: "l"(p), "f"(v.x), "f"(v.y), "f"(v.z), "f"(v.w) : "memory");
}
__device__ __forceinline__ float leaky(float v) { return v > 0.f ? v : 0.2f * v; }
__device__ __forceinline__ void acc8(float* a, uint4 u) {
    const __half2* h = (const __half2*)&u;
    float2 f0 = __half22float2(h[0]); a[0] += f0.x; a[1] += f0.y;
    float2 f1 = __half22float2(h[1]); a[2] += f1.x; a[3] += f1.y;
    float2 f2 = __half22float2(h[2]); a[4] += f2.x; a[5] += f2.y;
    float2 f3 = __half22float2(h[3]); a[6] += f3.x; a[7] += f3.y;
}
__device__ __forceinline__ uint4 hadd4(uint4 x, uint4 y) {
    uint4 r;
    asm("add.rn.f16x2 %0, %1, %2;" : "=r"(r.x) : "r"(x.x), "r"(y.x));
    asm("add.rn.f16x2 %0, %1, %2;" : "=r"(r.y) : "r"(x.y), "r"(y.y));
    asm("add.rn.f16x2 %0, %1, %2;" : "=r"(r.z) : "r"(x.z), "r"(y.z));
    asm("add.rn.f16x2 %0, %1, %2;" : "=r"(r.w) : "r"(x.w), "r"(y.w));
    return r;
}

// ---------------- single-pass bucket build ----------------
__global__ void k_fillb(const int* __restrict__ ei, int E) {
    if (blockIdx.x == 0) {
        for (int i = threadIdx.x; i < 6 * 64; i += blockDim.x) g_bn[i] = 0.f;
    }
    int t = blockIdx.x * blockDim.x + threadIdx.x;
    int i0 = t * 8;
    if (i0 + 7 < E) {
        int4 sa = *(const int4*)(ei + i0);
        int4 sb = *(const int4*)(ei + i0 + 4);
        int4 da = *(const int4*)(ei + E + i0);
        int4 db = *(const int4*)(ei + E + i0 + 4);
        int p0 = atomicAdd(&g_deg[da.x], 1);
        int p1 = atomicAdd(&g_deg[da.y], 1);
        int p2 = atomicAdd(&g_deg[da.z], 1);
        int p3 = atomicAdd(&g_deg[da.w], 1);
        int p4 = atomicAdd(&g_deg[db.x], 1);
        int p5 = atomicAdd(&g_deg[db.y], 1);
        int p6 = atomicAdd(&g_deg[db.z], 1);
        int p7 = atomicAdd(&g_deg[db.w], 1);
        g_csrc[da.x * BUCKET + p0] = sa.x;
        g_csrc[da.y * BUCKET + p1] = sa.y;
        g_csrc[da.z * BUCKET + p2] = sa.z;
        g_csrc[da.w * BUCKET + p3] = sa.w;
        g_csrc[db.x * BUCKET + p4] = sb.x;
        g_csrc[db.y * BUCKET + p5] = sb.y;
        g_csrc[db.z * BUCKET + p6] = sb.z;
        g_csrc[db.w * BUCKET + p7] = sb.w;
    } else {
        for (int i = i0; i < E; i++) {
            int d = ei[E + i];
            int p = atomicAdd(&g_deg[d], 1);
            g_csrc[d * BUCKET + p] = ei[i];
        }
    }
}

// dinv from deg + x' = x*dinv -> 32 halfs padded. Nn*4 threads.
__global__ void k_dinvconvx(const float* __restrict__ x) {
    int t = blockIdx.x * blockDim.x + threadIdx.x;
    if (t >= Nn * 4) return;
    int node = t >> 2, q = t & 3;
    float di = rsqrtf((float)(g_deg[node] + 1));   // +1 self loop
    if (q == 0) g_dinv[node] = di;
    __half hv[8];
#pragma unroll
    for (int k = 0; k < 8; k++) {
        int c = q * 8 + k;
        float v = (c < 20) ? x[node * 20 + c] * di : 0.f;
        hv[k] = __float2half_rn(v);
    }
    g_xh[node * 4 + q] = *(const uint4*)hv;
}

// ---------------- GCN bucket gather (half rows, dinv pre-folded, 2-stage pipeline) ----------------
template <int U4, bool STATS>
__global__ void k_gcn(const uint4* __restrict__ rows, const float* __restrict__ b,
                      float4* __restrict__ out4, float* __restrict__ stat) {
    const int F = U4 * 8;
    __shared__ float ss[F], sq[F];
    if (STATS) {
        if (threadIdx.x < F) { ss[threadIdx.x] = 0.f; sq[threadIdx.x] = 0.f; }
        __syncthreads();
    }
    const int GPW = 32 / U4;
    int lane = threadIdx.x & 31, warp = threadIdx.x >> 5;
    int grp = lane / U4, j = lane % U4;
    int node = (blockIdx.x * (blockDim.x >> 5) + warp) * GPW + grp;
    bool act = node < Nn;
    float a[8] = {0, 0, 0, 0, 0, 0, 0, 0};
    float di = 0.f;
    int r0 = 0, r1 = 0;
    if (act) {
        di = g_dinv[node];
        r0 = node * BUCKET;
        r1 = r0 + g_deg[node];
        acc8(a, __ldg(&rows[node * U4 + j]));  // self
    }
    int nb = (r1 - r0) >> 2;
    int k = r0 + (nb << 2);          // tail start
    if (nb >= 2) {
        int p0 = __ldg(&g_csrc[r0]),     p1 = __ldg(&g_csrc[r0 + 1]);
        int p2 = __ldg(&g_csrc[r0 + 2]), p3 = __ldg(&g_csrc[r0 + 3]);
        int q0 = __ldg(&g_csrc[r0 + 4]), q1 = __ldg(&g_csrc[r0 + 5]);
        int q2 = __ldg(&g_csrc[r0 + 6]), q3 = __ldg(&g_csrc[r0 + 7]);
        uint4 va0 = __ldg(&rows[p0 * U4 + j]);
        uint4 va1 = __ldg(&rows[p1 * U4 + j]);
        uint4 va2 = __ldg(&rows[p2 * U4 + j]);
        uint4 va3 = __ldg(&rows[p3 * U4 + j]);
        for (int t = 0; t < nb - 1; t++) {
            int c0, c1, c2, c3;
            bool more = (t + 2) < nb;
            if (more) {
                int base = r0 + (t + 2) * 4;
                c0 = __ldg(&g_csrc[base]);     c1 = __ldg(&g_csrc[base + 1]);
                c2 = __ldg(&g_csrc[base + 2]); c3 = __ldg(&g_csrc[base + 3]);
            }
            uint4 vb0 = __ldg(&rows[q0 * U4 + j]);
            uint4 vb1 = __ldg(&rows[q1 * U4 + j]);
            uint4 vb2 = __ldg(&rows[q2 * U4 + j]);
            uint4 vb3 = __ldg(&rows[q3 * U4 + j]);
            acc8(a, hadd4(va0, va1));
            acc8(a, hadd4(va2, va3));
            va0 = vb0; va1 = vb1; va2 = vb2; va3 = vb3;
            if (more) { q0 = c0; q1 = c1; q2 = c2; q3 = c3; }
        }
        acc8(a, hadd4(va0, va1));
        acc8(a, hadd4(va2, va3));
    } else if (nb == 1) {
        int p0 = __ldg(&g_csrc[r0]),     p1 = __ldg(&g_csrc[r0 + 1]);
        int p2 = __ldg(&g_csrc[r0 + 2]), p3 = __ldg(&g_csrc[r0 + 3]);
        uint4 va0 = __ldg(&rows[p0 * U4 + j]);
        uint4 va1 = __ldg(&rows[p1 * U4 + j]);
        uint4 va2 = __ldg(&rows[p2 * U4 + j]);
        uint4 va3 = __ldg(&rows[p3 * U4 + j]);
        acc8(a, hadd4(va0, va1));
        acc8(a, hadd4(va2, va3));
    }
    for (; k < r1; k++) acc8(a, __ldg(&rows[__ldg(&g_csrc[k]) * U4 + j]));

    float o[8];
    float4 b0 = b ? __ldg(&((const float4*)b)[j * 2])     : make_float4(0, 0, 0, 0);
    float4 b1 = b ? __ldg(&((const float4*)b)[j * 2 + 1]) : make_float4(0, 0, 0, 0);
#pragma unroll
    for (int c = 0; c < 8; c++) {
        float bb = (c < 4) ? (&b0.x)[c] : (&b1.x)[c - 4];
        o[c] = act ? (a[c] * di + bb) : 0.f;
    }
    if (act) {
        out4[node * (U4 * 2) + j * 2]     = make_float4(o[0], o[1], o[2], o[3]);
        out4[node * (U4 * 2) + j * 2 + 1] = make_float4(o[4], o[5], o[6], o[7]);
    }
    if (STATS) {
        float q[8];
#pragma unroll
        for (int c = 0; c < 8; c++) q[c] = o[c] * o[c];
#pragma unroll
        for (int off = U4; off < 32; off <<= 1) {
#pragma unroll
            for (int c = 0; c < 8; c++) {
                o[c] += __shfl_xor_sync(~0u, o[c], off);
                q[c] += __shfl_xor_sync(~0u, q[c], off);
            }
        }
        if (grp == 0) {
#pragma unroll
            for (int c = 0; c < 8; c++) {
                atomicAdd(&ss[j * 8 + c], o[c]);
                atomicAdd(&sq[j * 8 + c], q[c]);
            }
        }
        __syncthreads();
        if (threadIdx.x < F) {
            atomicAdd(&stat[threadIdx.x], ss[threadIdx.x]);
            atomicAdd(&stat[F + threadIdx.x], sq[threadIdx.x]);
        }
    }
}

// ---------------- GEMM layer 1 (vectorized): thread = (node, float4-of-outputs) ----------------
// block 256 = 16 nodes x 16 fo4-groups. Nn % 16 == 0.
__global__ void k_gemm1(const float* __restrict__ h, const float* __restrict__ W,
                        const float* __restrict__ bias, float4* __restrict__ out,
                        float* __restrict__ stat) {
    __shared__ float4 Ws[20 * 16];
    __shared__ float ss[64], sq[64];
    int tid = threadIdx.x;
    for (int i = tid; i < 20 * 16; i += 256) Ws[i] = ((const float4*)W)[i];
    if (tid < 64) { ss[tid] = 0.f; sq[tid] = 0.f; }
    __syncthreads();
    int nl = tid >> 4, fo4 = tid & 15;
    int node = blockIdx.x * 16 + nl;           // Nn/16 = 6250 exact
    const float4* hr = (const float4*)(h + node * 32);
    float4 f0 = hr[0], f1 = hr[1], f2 = hr[2], f3 = hr[3], f4 = hr[4];
    float hf[20] = {f0.x, f0.y, f0.z, f0.w, f1.x, f1.y, f1.z, f1.w,
                    f2.x, f2.y, f2.z, f2.w, f3.x, f3.y, f3.z, f3.w,
                    f4.x, f4.y, f4.z, f4.w};
    float4 acc = __ldg(&((const float4*)bias)[fo4]);
#pragma unroll
    for (int fi = 0; fi < 20; fi++) {
        float4 w = Ws[fi * 16 + fo4];
        float a = hf[fi];
        acc.x += a * w.x; acc.y += a * w.y; acc.z += a * w.z; acc.w += a * w.w;
    }
    out[node * 16 + fo4] = acc;
    // stats: combine the warp's two nodes (xor 16), lanes 0-15 flush to shared
    float4 s2 = make_float4(acc.x * acc.x, acc.y * acc.y, acc.z * acc.z, acc.w * acc.w);
    acc.x += __shfl_xor_sync(~0u, acc.x, 16); s2.x += __shfl_xor_sync(~0u, s2.x, 16);
    acc.y += __shfl_xor_sync(~0u, acc.y, 16); s2.y += __shfl_xor_sync(~0u, s2.y, 16);
    acc.z += __shfl_xor_sync(~0u, acc.z, 16); s2.z += __shfl_xor_sync(~0u, s2.z, 16);
    acc.w += __shfl_xor_sync(~0u, acc.w, 16); s2.w += __shfl_xor_sync(~0u, s2.w, 16);
    if ((tid & 31) < 16) {
        atomicAdd(&ss[fo4 * 4 + 0], acc.x); atomicAdd(&sq[fo4 * 4 + 0], s2.x);
        atomicAdd(&ss[fo4 * 4 + 1], acc.y); atomicAdd(&sq[fo4 * 4 + 1], s2.y);
        atomicAdd(&ss[fo4 * 4 + 2], acc.z); atomicAdd(&sq[fo4 * 4 + 2], s2.z);
        atomicAdd(&ss[fo4 * 4 + 3], acc.w); atomicAdd(&sq[fo4 * 4 + 3], s2.w);
    }
    __syncthreads();
    if (tid < 64) {
        atomicAdd(&stat[tid], ss[tid]);
        atomicAdd(&stat[64 + tid], sq[tid]);
    }
}

// ---------------- fused BN+ReLU + GEMM + *dinv -> half (vectorized) ----------------
// block 256 = NODES x (FO/4). Hs padded stride FI+4 (bank-conflict-free broadcast).
template <int FI, int FO>
__global__ void k_gemmbn(const float* __restrict__ acc, const float* __restrict__ stat,
                         const float* __restrict__ g, const float* __restrict__ be,
                         const float* __restrict__ W, uint2* __restrict__ out) {
    const int G4 = FO / 4;
    const int NODES = 256 / G4;
    const int HP = FI + 4;                 // padded row stride (words), 16B-aligned
    __shared__ float4 Ws[FI * G4];
    __shared__ float Hs[NODES * HP];
    __shared__ float sc[FI], sh[FI];
    int tid = threadIdx.x;
    for (int i = tid; i < FI * G4; i += 256) Ws[i] = ((const float4*)W)[i];
    if (tid < FI) {
        const float invn = 1.0f / (float)Nn;
        float mu  = stat[tid] * invn;
        float var = stat[FI + tid] * invn - mu * mu;
        float kk  = g[tid] * rsqrtf(var + BN_EPS);
        sc[tid] = kk;
        sh[tid] = be[tid] - mu * kk;
    }
    __syncthreads();
    int node0 = blockIdx.x * NODES;
    int nv = Nn - node0; if (nv > NODES) nv = NODES;
    // stage BN+ReLU'd activations, float4 global reads, padded shared writes
    for (int i = tid; i < nv * (FI / 4); i += 256) {
        int r = i / (FI / 4), q = i % (FI / 4);
        float4 v = ((const float4*)(acc + (node0 + r) * FI))[q];
        int f = q * 4;
        v.x = fmaxf(v.x * sc[f + 0] + sh[f + 0], 0.f);
        v.y = fmaxf(v.y * sc[f + 1] + sh[f + 1], 0.f);
        v.z = fmaxf(v.z * sc[f + 2] + sh[f + 2], 0.f);
        v.w = fmaxf(v.w * sc[f + 3] + sh[f + 3], 0.f);
        *(float4*)&Hs[r * HP + f] = v;
    }
    __syncthreads();
    int nl = tid / G4, fo4 = tid % G4;
    int node = node0 + nl;
    if (nl >= nv) return;
    const float* hrow = &Hs[nl * HP];
    float4 a4 = make_float4(0.f, 0.f, 0.f, 0.f);
#pragma unroll
    for (int fi = 0; fi < FI; fi++) {
        float a = hrow[fi];
        float4 w = Ws[fi * G4 + fo4];
        a4.x += a * w.x; a4.y += a * w.y; a4.z += a * w.z; a4.w += a * w.w;
    }
    float di = g_dinv[node];
    a4.x *= di; a4.y *= di; a4.z *= di; a4.w *= di;
    __half2 h0 = __floats2half2_rn(a4.x, a4.y);
    __half2 h1 = __floats2half2_rn(a4.z, a4.w);
    uint2 u;
    u.x = *(unsigned*)&h0;
    u.y = *(unsigned*)&h1;
    out[node * G4 + fo4] = u;
}

// was[k][h] = sum_c Wg[k][h*16+c]*att_src[h][c]; wad likewise. 128 threads.
__global__ void k_prep(const float* __restrict__ Wg, const float* __restrict__ asrc,
                       const float* __restrict__ adst) {
    int t = threadIdx.x;
    int k = t >> 3, h = t & 7;
    float s1 = 0.f, s2 = 0.f;
#pragma unroll
    for (int c = 0; c < 16; c++) {
        float w = Wg[k * 128 + h * 16 + c];
        s1 += w * asrc[h * 16 + c];
        s2 += w * adst[h * 16 + c];
    }
    g_was[k * 8 + h] = s1;
    g_wad[k * 8 + h] = s2;
}

// fused BN+ReLU(layer3) + h3->half + attention dots. block=256 -> 16 nodes. Nn%16==0.
__global__ void k_bn3att(const float* __restrict__ acc3, const float* __restrict__ stat,
                         const float* __restrict__ g, const float* __restrict__ be) {
    __shared__ float sv[16][17];
    __shared__ float sw[2][16][8];
    int t = threadIdx.x;
    if (t < 128) { sw[0][t >> 3][t & 7] = g_was[t]; sw[1][t >> 3][t & 7] = g_wad[t]; }
    int node0 = blockIdx.x * 16;
    int nl = t >> 4, f = t & 15;
    const float invn = 1.0f / (float)Nn;
    float mu  = stat[f] * invn;
    float var = stat[16 + f] * invn - mu * mu;
    float v = (acc3[(node0 + nl) * 16 + f] - mu) * rsqrtf(var + BN_EPS) * g[f] + be[f];
    v = fmaxf(v, 0.f);
    sv[nl][f] = v;
    __syncthreads();
    if (t < 64) {
        int n2 = t >> 2, q = t & 3;
        __half2 p0 = __floats2half2_rn(sv[n2][q * 4 + 0], sv[n2][q * 4 + 1]);
        __half2 p1 = __floats2half2_rn(sv[n2][q * 4 + 2], sv[n2][q * 4 + 3]);
        uint2 u;
        u.x = *(unsigned*)&p0;
        u.y = *(unsigned*)&p1;
        g_h3h[(node0 + n2) * 4 + q] = u;
    }
    if (t < 128) {
        int n3 = t >> 3, h = t & 7;
        float s1 = 0.f, s2 = 0.f;
#pragma unroll
        for (int k = 0; k < 16; k++) {
            float hv = sv[n3][k];
            s1 += hv * sw[0][k][h];
            s2 += hv * sw[1][k][h];
        }
        g_as[(node0 + n3) * 8 + h] = s1;
        g_ad[(node0 + n3) * 8 + h] = s2;
    }
}

// ---------------- fused GAT (no-max softmax) + deg reset epilogue ----------------
__device__ __forceinline__ void gat_step(float l, uint2 u, float& sum, float4& acc) {
    float e = __expf(l);
    float2 f0 = __half22float2(*(const __half2*)&u.x);
    float2 f1 = __half22float2(*(const __half2*)&u.y);
    sum += e;
    acc.x += e * f0.x; acc.y += e * f0.y; acc.z += e * f1.x; acc.w += e * f1.y;
}

__global__ void k_gat(const float* __restrict__ Wg, const float* __restrict__ bg,
                      const int* __restrict__ batch) {
    __shared__ float Wgs[16 * 128];
    __shared__ float buf[8][8][16];     // [warp][head][k]
    for (int i = threadIdx.x; i < 16 * 128; i += blockDim.x) Wgs[i] = Wg[i];
    __syncthreads();
    int lane = threadIdx.x & 31, warp = threadIdx.x >> 5;
    int d = blockIdx.x * 8 + warp;      // grid = Nn/8 exact
    int h = lane >> 2, j = lane & 3;
    float adh = g_ad[d * 8 + h];
    int r0 = d * BUCKET, r1 = r0 + g_deg[d];

    float e0 = __expf(leaky(g_as[d * 8 + h] + adh));
    float sum = e0;
    uint2 su = __ldg(&g_h3h[d * 4 + j]);
    float2 sf0 = __half22float2(*(const __half2*)&su.x);
    float2 sf1 = __half22float2(*(const __half2*)&su.y);
    float4 acc = make_float4(e0 * sf0.x, e0 * sf0.y, e0 * sf1.x, e0 * sf1.y);

    int nb = (r1 - r0) >> 2;
    int k = r0 + (nb << 2);             // tail start
    if (nb >= 2) {
        int p0 = __ldg(&g_csrc[r0]),     p1 = __ldg(&g_csrc[r0 + 1]);
        int p2 = __ldg(&g_csrc[r0 + 2]), p3 = __ldg(&g_csrc[r0 + 3]);
        int q0 = __ldg(&g_csrc[r0 + 4]), q1 = __ldg(&g_csrc[r0 + 5]);
        int q2 = __ldg(&g_csrc[r0 + 6]), q3 = __ldg(&g_csrc[r0 + 7]);
        float la0 = __ldg(&g_as[p0 * 8 + h]), la1 = __ldg(&g_as[p1 * 8 + h]);
        float la2 = __ldg(&g_as[p2 * 8 + h]), la3 = __ldg(&g_as[p3 * 8 + h]);
        uint2 ua0 = __ldg(&g_h3h[p0 * 4 + j]);
        uint2 ua1 = __ldg(&g_h3h[p1 * 4 + j]);
        uint2 ua2 = __ldg(&g_h3h[p2 * 4 + j]);
        uint2 ua3 = __ldg(&g_h3h[p3 * 4 + j]);
        for (int t = 0; t < nb - 1; t++) {
            int c0, c1, c2, c3;
            bool more = (t + 2) < nb;
            if (more) {
                int base = r0 + (t + 2) * 4;
                c0 = __ldg(&g_csrc[base]);     c1 = __ldg(&g_csrc[base + 1]);
                c2 = __ldg(&g_csrc[base + 2]); c3 = __ldg(&g_csrc[base + 3]);
            }
            float lb0 = __ldg(&g_as[q0 * 8 + h]), lb1 = __ldg(&g_as[q1 * 8 + h]);
            float lb2 = __ldg(&g_as[q2 * 8 + h]), lb3 = __ldg(&g_as[q3 * 8 + h]);
            uint2 ub0 = __ldg(&g_h3h[q0 * 4 + j]);
            uint2 ub1 = __ldg(&g_h3h[q1 * 4 + j]);
            uint2 ub2 = __ldg(&g_h3h[q2 * 4 + j]);
            uint2 ub3 = __ldg(&g_h3h[q3 * 4 + j]);
            gat_step(leaky(la0 + adh), ua0, sum, acc);
            gat_step(leaky(la1 + adh), ua1, sum, acc);
            gat_step(leaky(la2 + adh), ua2, sum, acc);
            gat_step(leaky(la3 + adh), ua3, sum, acc);
            la0 = lb0; la1 = lb1; la2 = lb2; la3 = lb3;
            ua0 = ub0; ua1 = ub1; ua2 = ub2; ua3 = ub3;
            if (more) { q0 = c0; q1 = c1; q2 = c2; q3 = c3; }
        }
        gat_step(leaky(la0 + adh), ua0, sum, acc);
        gat_step(leaky(la1 + adh), ua1, sum, acc);
        gat_step(leaky(la2 + adh), ua2, sum, acc);
        gat_step(leaky(la3 + adh), ua3, sum, acc);
    } else if (nb == 1) {
        int p0 = __ldg(&g_csrc[r0]),     p1 = __ldg(&g_csrc[r0 + 1]);
        int p2 = __ldg(&g_csrc[r0 + 2]), p3 = __ldg(&g_csrc[r0 + 3]);
        float la0 = __ldg(&g_as[p0 * 8 + h]), la1 = __ldg(&g_as[p1 * 8 + h]);
        float la2 = __ldg(&g_as[p2 * 8 + h]), la3 = __ldg(&g_as[p3 * 8 + h]);
        uint2 ua0 = __ldg(&g_h3h[p0 * 4 + j]);
        uint2 ua1 = __ldg(&g_h3h[p1 * 4 + j]);
        uint2 ua2 = __ldg(&g_h3h[p2 * 4 + j]);
        uint2 ua3 = __ldg(&g_h3h[p3 * 4 + j]);
        gat_step(leaky(la0 + adh), ua0, sum, acc);
        gat_step(leaky(la1 + adh), ua1, sum, acc);
        gat_step(leaky(la2 + adh), ua2, sum, acc);
        gat_step(leaky(la3 + adh), ua3, sum, acc);
    }
    for (; k < r1; k++) {
        int s = __ldg(&g_csrc[k]);
        float l = leaky(__ldg(&g_as[s * 8 + h]) + adh);
        gat_step(l, __ldg(&g_h3h[s * 4 + j]), sum, acc);
    }
    float sc = 0.125f / sum;
    buf[warp][h][j * 4 + 0] = acc.x * sc;
    buf[warp][h][j * 4 + 1] = acc.y * sc;
    buf[warp][h][j * 4 + 2] = acc.z * sc;
    buf[warp][h][j * 4 + 3] = acc.w * sc;
    __syncwarp();

    if (lane == 0) g_deg[d] = 0;   // reset for next call

    if (lane < 4) {
        float4 hg = ((const float4*)bg)[lane];
#pragma unroll
        for (int hh = 0; hh < 8; hh++) {
#pragma unroll
            for (int kk = 0; kk < 16; kk++) {
                float a = buf[warp][hh][kk];
                const float4 w = *(const float4*)&Wgs[kk * 128 + hh * 16 + lane * 4];
                hg.x += a * w.x; hg.y += a * w.y; hg.z += a * w.z; hg.w += a * w.w;
            }
        }
        red4(((float4*)g_pool) + batch[d] * 4 + lane, hg);
    }
}

// one thread per graph: out[g] = pool[g]@Wf + bf, then zero its pool entries
__global__ void k_final(const float* __restrict__ Wf, const float* __restrict__ bf,
                        float* __restrict__ out) {
    int gg = blockIdx.x * blockDim.x + threadIdx.x;
    if (gg >= Gg) return;
    float p[16];
    float4* pp = (float4*)&g_pool[gg * 16];
#pragma unroll
    for (int q = 0; q < 4; q++) {
        float4 v = pp[q];
        p[q * 4 + 0] = v.x; p[q * 4 + 1] = v.y; p[q * 4 + 2] = v.z; p[q * 4 + 3] = v.w;
        pp[q] = make_float4(0.f, 0.f, 0.f, 0.f);
    }
#pragma unroll
    for (int k = 0; k < 3; k++) {
        float s = bf[k];
#pragma unroll
        for (int c = 0; c < 16; c++) s += p[c] * Wf[c * 3 + k];
        out[gg * 3 + k] = s;
    }
}

// ---------------- launch ----------------
static inline void* symaddr(const void* s) { void* p = nullptr; cudaGetSymbolAddress(&p, s); return p; }

extern "C" void kernel_launch(void* const* d_in, const int* in_sizes, int n_in,
                              void* d_out, int out_size) {
    const float* x       = (const float*)d_in[0];
    const int*   ei      = (const int*)  d_in[1];
    const int*   batch   = (const int*)  d_in[2];
    const float* W1 = (const float*)d_in[3],  *b1 = (const float*)d_in[4];
    const float* g1 = (const float*)d_in[5],  *be1= (const float*)d_in[6];
    const float* W2 = (const float*)d_in[7],  *b2 = (const float*)d_in[8];
    const float* g2 = (const float*)d_in[9],  *be2= (const float*)d_in[10];
    const float* W3 = (const float*)d_in[11], *b3 = (const float*)d_in[12];
    const float* g3 = (const float*)d_in[13], *be3= (const float*)d_in[14];
    const float* Wg = (const float*)d_in[15];
    const float* att_src = (const float*)d_in[16];
    const float* att_dst = (const float*)d_in[17];
    const float* bg = (const float*)d_in[18];
    const float* Wf = (const float*)d_in[19], *bf = (const float*)d_in[20];
    float* out = (float*)d_out;
    const int E = in_sizes[1] / 2;

    float* axp  = (float*)symaddr(g_axp);
    float* acc1 = (float*)symaddr(g_acc1);
    float* acc2 = (float*)symaddr(g_acc2);
    float* acc3 = (float*)symaddr(g_acc3);
    float* bn   = (float*)symaddr(g_bn);
    uint4* xh   = (uint4*)symaddr(g_xh);
    uint2* t2h  = (uint2*)symaddr(g_t2h);
    uint2* t3h  = (uint2*)symaddr(g_t3h);

    const int B = 256;
    // ---- bucket adjacency build ----
    k_fillb<<<(E / 8 + B) / B, B>>>(ei, E);
    k_dinvconvx<<<(Nn * 4 + B - 1) / B, B>>>(x);

    // ---- GCN layer 1: aggregate x' (half), vectorized GEMM 20->64 (+stats) ----
    k_gcn<4, false><<<(Nn + 63) / 64, B>>>(xh, nullptr, (float4*)axp, nullptr);
    k_gemm1<<<Nn / 16, B>>>(axp, W1, b1, (float4*)acc1, bn + 0);

    // ---- GCN layer 2: fused BN1+ReLU+GEMM 64->32 (*dinv, half), aggregate (+stats) ----
    k_gemmbn<64, 32><<<(Nn + 31) / 32, B>>>(acc1, bn + 0, g1, be1, W2, t2h);
    k_gcn<4, true><<<(Nn + 63) / 64, B>>>((const uint4*)t2h, b2, (float4*)acc2, bn + 128);

    // ---- GCN layer 3: fused BN2+ReLU+GEMM 32->16 (*dinv, half), aggregate (+stats) ----
    k_gemmbn<32, 16><<<(Nn + 63) / 64, B>>>(acc2, bn + 128, g2, be2, W3, t3h);
    k_gcn<2, true><<<(Nn + 127) / 128, B>>>((const uint4*)t3h, b3, (float4*)acc3, bn + 256);

    // ---- BN3 + attention dots fused, then no-max GAT (+deg reset) ----
    k_prep<<<1, 128>>>(Wg, att_src, att_dst);
    k_bn3att<<<Nn / 16, B>>>(acc3, bn + 256, g3, be3);
    k_gat<<<Nn / 8, B>>>(Wg, bg, batch);

    // ---- classifier (+pool reset) ----
    k_final<<<(Gg + B - 1) / B, B>>>(Wf, bf, out);
}

// round 15
// speedup vs baseline: 1.2528x; 1.0037x over previous
#include <cuda_runtime.h>
#include <cuda_fp16.h>

#define Nn 100000
#define MAXE 3200000
#define Gg 5000
#define BUCKET 96
#define BN_EPS 1e-5f

// ---------------- scratch (static device globals; zero-initialized at load) ----------------
__device__ int      g_deg [Nn];          // reset by k_gat epilogue each call
__device__ int      g_csrc[Nn * BUCKET]; // bucketed adjacency (src lists per dst)
__device__ float    g_dinv[Nn];
__device__ uint4    g_xh  [Nn * 4];     // x' = x*dinv, padded to 32 halfs
__device__ float    g_axp [Nn * 32];    // aggregated x', padded 32 floats
__device__ uint4    g_t2h [Nn * 4];     // t2' = bnrelu(acc1)@W2*dinv, 32 halfs
__device__ uint4    g_t3h [Nn * 2];     // t3' = bnrelu(acc2)@W3*dinv, 16 halfs
__device__ uint2    g_h3h [Nn * 4];     // h3 post-BN, 16 halfs
__device__ float    g_acc1[Nn * 64];
__device__ float    g_acc2[Nn * 32];
__device__ float    g_acc3[Nn * 16];
__device__ float    g_as  [Nn * 8];
__device__ float    g_ad  [Nn * 8];
__device__ float    g_was [16 * 8];
__device__ float    g_wad [16 * 8];
__device__ float    g_pool[Gg * 16];    // reset by k_final after reading
__device__ float    g_bn  [6 * 64];     // zeroed by k_fillb block 0 each call

// ---------------- helpers ----------------
__device__ __forceinline__ void red4(float4* p, float4 v) {
    asm volatile("red.global.add.v4.f32 [%0], {%1,%2,%3,%4};"
                 :: "l"(p), "f"(v.x), "f"(v.y), "f"(v.z), "f"(v.w) : "memory");
}
__device__ __forceinline__ float leaky(float v) { return v > 0.f ? v : 0.2f * v; }
__device__ __forceinline__ void acc8(float* a, uint4 u) {
    const __half2* h = (const __half2*)&u;
    float2 f0 = __half22float2(h[0]); a[0] += f0.x; a[1] += f0.y;
    float2 f1 = __half22float2(h[1]); a[2] += f1.x; a[3] += f1.y;
    float2 f2 = __half22float2(h[2]); a[4] += f2.x; a[5] += f2.y;
    float2 f3 = __half22float2(h[3]); a[6] += f3.x; a[7] += f3.y;
}
__device__ __forceinline__ uint4 hadd4(uint4 x, uint4 y) {
    uint4 r;
    asm("add.rn.f16x2 %0, %1, %2;" : "=r"(r.x) : "r"(x.x), "r"(y.x));
    asm("add.rn.f16x2 %0, %1, %2;" : "=r"(r.y) : "r"(x.y), "r"(y.y));
    asm("add.rn.f16x2 %0, %1, %2;" : "=r"(r.z) : "r"(x.z), "r"(y.z));
    asm("add.rn.f16x2 %0, %1, %2;" : "=r"(r.w) : "r"(x.w), "r"(y.w));
    return r;
}

// ---------------- single-pass bucket build ----------------
__global__ void k_fillb(const int* __restrict__ ei, int E) {
    if (blockIdx.x == 0) {
        for (int i = threadIdx.x; i < 6 * 64; i += blockDim.x) g_bn[i] = 0.f;
    }
    int t = blockIdx.x * blockDim.x + threadIdx.x;
    int i0 = t * 8;
    if (i0 + 7 < E) {
        int4 sa = *(const int4*)(ei + i0);
        int4 sb = *(const int4*)(ei + i0 + 4);
        int4 da = *(const int4*)(ei + E + i0);
        int4 db = *(const int4*)(ei + E + i0 + 4);
        int p0 = atomicAdd(&g_deg[da.x], 1);
        int p1 = atomicAdd(&g_deg[da.y], 1);
        int p2 = atomicAdd(&g_deg[da.z], 1);
        int p3 = atomicAdd(&g_deg[da.w], 1);
        int p4 = atomicAdd(&g_deg[db.x], 1);
        int p5 = atomicAdd(&g_deg[db.y], 1);
        int p6 = atomicAdd(&g_deg[db.z], 1);
        int p7 = atomicAdd(&g_deg[db.w], 1);
        g_csrc[da.x * BUCKET + p0] = sa.x;
        g_csrc[da.y * BUCKET + p1] = sa.y;
        g_csrc[da.z * BUCKET + p2] = sa.z;
        g_csrc[da.w * BUCKET + p3] = sa.w;
        g_csrc[db.x * BUCKET + p4] = sb.x;
        g_csrc[db.y * BUCKET + p5] = sb.y;
        g_csrc[db.z * BUCKET + p6] = sb.z;
        g_csrc[db.w * BUCKET + p7] = sb.w;
    } else {
        for (int i = i0; i < E; i++) {
            int d = ei[E + i];
            int p = atomicAdd(&g_deg[d], 1);
            g_csrc[d * BUCKET + p] = ei[i];
        }
    }
}

// dinv from deg + x' = x*dinv -> 32 halfs padded. Nn*4 threads.
__global__ void k_dinvconvx(const float* __restrict__ x) {
    int t = blockIdx.x * blockDim.x + threadIdx.x;
    if (t >= Nn * 4) return;
    int node = t >> 2, q = t & 3;
    float di = rsqrtf((float)(g_deg[node] + 1));   // +1 self loop
    if (q == 0) g_dinv[node] = di;
    __half hv[8];
#pragma unroll
    for (int k = 0; k < 8; k++) {
        int c = q * 8 + k;
        float v = (c < 20) ? x[node * 20 + c] * di : 0.f;
        hv[k] = __float2half_rn(v);
    }
    g_xh[node * 4 + q] = *(const uint4*)hv;
}

// ---------------- GCN bucket gather (half rows, dinv pre-folded, 2-stage pipeline) ----------------
template <int U4, bool STATS>
__global__ void __launch_bounds__(256, 4)
k_gcn(const uint4* __restrict__ rows, const float* __restrict__ b,
      float4* __restrict__ out4, float* __restrict__ stat) {
    const int F = U4 * 8;
    __shared__ float ss[F], sq[F];
    if (STATS) {
        if (threadIdx.x < F) { ss[threadIdx.x] = 0.f; sq[threadIdx.x] = 0.f; }
        __syncthreads();
    }
    const int GPW = 32 / U4;
    int lane = threadIdx.x & 31, warp = threadIdx.x >> 5;
    int grp = lane / U4, j = lane % U4;
    int node = (blockIdx.x * (blockDim.x >> 5) + warp) * GPW + grp;
    bool act = node < Nn;
    float a[8] = {0, 0, 0, 0, 0, 0, 0, 0};
    float di = 0.f;
    int r0 = 0, r1 = 0;
    if (act) {
        di = g_dinv[node];
        r0 = node * BUCKET;
        r1 = r0 + g_deg[node];
        acc8(a, __ldg(&rows[node * U4 + j]));  // self
    }
    int nb = (r1 - r0) >> 2;
    int k = r0 + (nb << 2);          // tail start
    if (nb >= 2) {
        int p0 = __ldg(&g_csrc[r0]),     p1 = __ldg(&g_csrc[r0 + 1]);
        int p2 = __ldg(&g_csrc[r0 + 2]), p3 = __ldg(&g_csrc[r0 + 3]);
        int q0 = __ldg(&g_csrc[r0 + 4]), q1 = __ldg(&g_csrc[r0 + 5]);
        int q2 = __ldg(&g_csrc[r0 + 6]), q3 = __ldg(&g_csrc[r0 + 7]);
        uint4 va0 = __ldg(&rows[p0 * U4 + j]);
        uint4 va1 = __ldg(&rows[p1 * U4 + j]);
        uint4 va2 = __ldg(&rows[p2 * U4 + j]);
        uint4 va3 = __ldg(&rows[p3 * U4 + j]);
        for (int t = 0; t < nb - 1; t++) {
            int c0, c1, c2, c3;
            bool more = (t + 2) < nb;
            if (more) {
                int base = r0 + (t + 2) * 4;
                c0 = __ldg(&g_csrc[base]);     c1 = __ldg(&g_csrc[base + 1]);
                c2 = __ldg(&g_csrc[base + 2]); c3 = __ldg(&g_csrc[base + 3]);
            }
            uint4 vb0 = __ldg(&rows[q0 * U4 + j]);
            uint4 vb1 = __ldg(&rows[q1 * U4 + j]);
            uint4 vb2 = __ldg(&rows[q2 * U4 + j]);
            uint4 vb3 = __ldg(&rows[q3 * U4 + j]);
            acc8(a, hadd4(va0, va1));
            acc8(a, hadd4(va2, va3));
            va0 = vb0; va1 = vb1; va2 = vb2; va3 = vb3;
            if (more) { q0 = c0; q1 = c1; q2 = c2; q3 = c3; }
        }
        acc8(a, hadd4(va0, va1));
        acc8(a, hadd4(va2, va3));
    } else if (nb == 1) {
        int p0 = __ldg(&g_csrc[r0]),     p1 = __ldg(&g_csrc[r0 + 1]);
        int p2 = __ldg(&g_csrc[r0 + 2]), p3 = __ldg(&g_csrc[r0 + 3]);
        uint4 va0 = __ldg(&rows[p0 * U4 + j]);
        uint4 va1 = __ldg(&rows[p1 * U4 + j]);
        uint4 va2 = __ldg(&rows[p2 * U4 + j]);
        uint4 va3 = __ldg(&rows[p3 * U4 + j]);
        acc8(a, hadd4(va0, va1));
        acc8(a, hadd4(va2, va3));
    }
    for (; k < r1; k++) acc8(a, __ldg(&rows[__ldg(&g_csrc[k]) * U4 + j]));

    float o[8];
    float4 b0 = b ? __ldg(&((const float4*)b)[j * 2])     : make_float4(0, 0, 0, 0);
    float4 b1 = b ? __ldg(&((const float4*)b)[j * 2 + 1]) : make_float4(0, 0, 0, 0);
#pragma unroll
    for (int c = 0; c < 8; c++) {
        float bb = (c < 4) ? (&b0.x)[c] : (&b1.x)[c - 4];
        o[c] = act ? (a[c] * di + bb) : 0.f;
    }
    if (act) {
        out4[node * (U4 * 2) + j * 2]     = make_float4(o[0], o[1], o[2], o[3]);
        out4[node * (U4 * 2) + j * 2 + 1] = make_float4(o[4], o[5], o[6], o[7]);
    }
    if (STATS) {
        float q[8];
#pragma unroll
        for (int c = 0; c < 8; c++) q[c] = o[c] * o[c];
#pragma unroll
        for (int off = U4; off < 32; off <<= 1) {
#pragma unroll
            for (int c = 0; c < 8; c++) {
                o[c] += __shfl_xor_sync(~0u, o[c], off);
                q[c] += __shfl_xor_sync(~0u, q[c], off);
            }
        }
        if (grp == 0) {
#pragma unroll
            for (int c = 0; c < 8; c++) {
                atomicAdd(&ss[j * 8 + c], o[c]);
                atomicAdd(&sq[j * 8 + c], q[c]);
            }
        }
        __syncthreads();
        if (threadIdx.x < F) {
            atomicAdd(&stat[threadIdx.x], ss[threadIdx.x]);
            atomicAdd(&stat[F + threadIdx.x], sq[threadIdx.x]);
        }
    }
}

// ---------------- GEMM layer 1 (vectorized + shared-staged rows) ----------------
// block 256 = 16 nodes x 16 fo4-groups. Nn % 16 == 0.
// Rows staged in shared (stride 36 floats: the warp's 2 nodes read banks fi / fi+4 -> conflict-free).
__global__ void k_gemm1(const float* __restrict__ h, const float* __restrict__ W,
                        const float* __restrict__ bias, float4* __restrict__ out,
                        float* __restrict__ stat) {
    __shared__ float4 Ws[20 * 16];
    __shared__ float Hs[16 * 36];
    __shared__ float ss[64], sq[64];
    int tid = threadIdx.x;
    for (int i = tid; i < 20 * 16; i += 256) Ws[i] = ((const float4*)W)[i];
    if (tid < 64) { ss[tid] = 0.f; sq[tid] = 0.f; }
    // stage 16 node rows (first 20 of 32 floats needed; load 8 float4 = full row, coalesced)
    if (tid < 128) {
        int r = tid >> 3, q = tid & 7;
        float4 v = ((const float4*)(h + (blockIdx.x * 16 + r) * 32))[q];
        *(float4*)&Hs[r * 36 + q * 4] = v;
    }
    __syncthreads();
    int nl = tid >> 4, fo4 = tid & 15;
    int node = blockIdx.x * 16 + nl;           // Nn/16 = 6250 exact
    const float* hrow = &Hs[nl * 36];
    float4 acc = __ldg(&((const float4*)bias)[fo4]);
#pragma unroll
    for (int fi = 0; fi < 20; fi++) {
        float4 w = Ws[fi * 16 + fo4];
        float a = hrow[fi];
        acc.x += a * w.x; acc.y += a * w.y; acc.z += a * w.z; acc.w += a * w.w;
    }
    out[node * 16 + fo4] = acc;
    // stats: combine the warp's two nodes (xor 16), lanes 0-15 flush to shared
    float4 s2 = make_float4(acc.x * acc.x, acc.y * acc.y, acc.z * acc.z, acc.w * acc.w);
    acc.x += __shfl_xor_sync(~0u, acc.x, 16); s2.x += __shfl_xor_sync(~0u, s2.x, 16);
    acc.y += __shfl_xor_sync(~0u, acc.y, 16); s2.y += __shfl_xor_sync(~0u, s2.y, 16);
    acc.z += __shfl_xor_sync(~0u, acc.z, 16); s2.z += __shfl_xor_sync(~0u, s2.z, 16);
    acc.w += __shfl_xor_sync(~0u, acc.w, 16); s2.w += __shfl_xor_sync(~0u, s2.w, 16);
    if ((tid & 31) < 16) {
        atomicAdd(&ss[fo4 * 4 + 0], acc.x); atomicAdd(&sq[fo4 * 4 + 0], s2.x);
        atomicAdd(&ss[fo4 * 4 + 1], acc.y); atomicAdd(&sq[fo4 * 4 + 1], s2.y);
        atomicAdd(&ss[fo4 * 4 + 2], acc.z); atomicAdd(&sq[fo4 * 4 + 2], s2.z);
        atomicAdd(&ss[fo4 * 4 + 3], acc.w); atomicAdd(&sq[fo4 * 4 + 3], s2.w);
    }
    __syncthreads();
    if (tid < 64) {
        atomicAdd(&stat[tid], ss[tid]);
        atomicAdd(&stat[64 + tid], sq[tid]);
    }
}

// ---------------- fused BN+ReLU + GEMM + *dinv -> half (vectorized) ----------------
template <int FI, int FO>
__global__ void k_gemmbn(const float* __restrict__ acc, const float* __restrict__ stat,
                         const float* __restrict__ g, const float* __restrict__ be,
                         const float* __restrict__ W, uint2* __restrict__ out) {
    const int G4 = FO / 4;
    const int NODES = 256 / G4;
    const int HP = FI + 4;
    __shared__ float4 Ws[FI * G4];
    __shared__ float Hs[NODES * HP];
    __shared__ float sc[FI], sh[FI];
    int tid = threadIdx.x;
    for (int i = tid; i < FI * G4; i += 256) Ws[i] = ((const float4*)W)[i];
    if (tid < FI) {
        const float invn = 1.0f / (float)Nn;
        float mu  = stat[tid] * invn;
        float var = stat[FI + tid] * invn - mu * mu;
        float kk  = g[tid] * rsqrtf(var + BN_EPS);
        sc[tid] = kk;
        sh[tid] = be[tid] - mu * kk;
    }
    __syncthreads();
    int node0 = blockIdx.x * NODES;
    int nv = Nn - node0; if (nv > NODES) nv = NODES;
    for (int i = tid; i < nv * (FI / 4); i += 256) {
        int r = i / (FI / 4), q = i % (FI / 4);
        float4 v = ((const float4*)(acc + (node0 + r) * FI))[q];
        int f = q * 4;
        v.x = fmaxf(v.x * sc[f + 0] + sh[f + 0], 0.f);
        v.y = fmaxf(v.y * sc[f + 1] + sh[f + 1], 0.f);
        v.z = fmaxf(v.z * sc[f + 2] + sh[f + 2], 0.f);
        v.w = fmaxf(v.w * sc[f + 3] + sh[f + 3], 0.f);
        *(float4*)&Hs[r * HP + f] = v;
    }
    __syncthreads();
    int nl = tid / G4, fo4 = tid % G4;
    int node = node0 + nl;
    if (nl >= nv) return;
    const float* hrow = &Hs[nl * HP];
    float4 a4 = make_float4(0.f, 0.f, 0.f, 0.f);
#pragma unroll
    for (int fi = 0; fi < FI; fi++) {
        float a = hrow[fi];
        float4 w = Ws[fi * G4 + fo4];
        a4.x += a * w.x; a4.y += a * w.y; a4.z += a * w.z; a4.w += a * w.w;
    }
    float di = g_dinv[node];
    a4.x *= di; a4.y *= di; a4.z *= di; a4.w *= di;
    __half2 h0 = __floats2half2_rn(a4.x, a4.y);
    __half2 h1 = __floats2half2_rn(a4.z, a4.w);
    uint2 u;
    u.x = *(unsigned*)&h0;
    u.y = *(unsigned*)&h1;
    out[node * G4 + fo4] = u;
}

// was[k][h] = sum_c Wg[k][h*16+c]*att_src[h][c]; wad likewise. 128 threads.
__global__ void k_prep(const float* __restrict__ Wg, const float* __restrict__ asrc,
                       const float* __restrict__ adst) {
    int t = threadIdx.x;
    int k = t >> 3, h = t & 7;
    float s1 = 0.f, s2 = 0.f;
#pragma unroll
    for (int c = 0; c < 16; c++) {
        float w = Wg[k * 128 + h * 16 + c];
        s1 += w * asrc[h * 16 + c];
        s2 += w * adst[h * 16 + c];
    }
    g_was[k * 8 + h] = s1;
    g_wad[k * 8 + h] = s2;
}

// fused BN+ReLU(layer3) + h3->half + attention dots. block=256 -> 16 nodes. Nn%16==0.
__global__ void k_bn3att(const float* __restrict__ acc3, const float* __restrict__ stat,
                         const float* __restrict__ g, const float* __restrict__ be) {
    __shared__ float sv[16][17];
    __shared__ float sw[2][16][8];
    int t = threadIdx.x;
    if (t < 128) { sw[0][t >> 3][t & 7] = g_was[t]; sw[1][t >> 3][t & 7] = g_wad[t]; }
    int node0 = blockIdx.x * 16;
    int nl = t >> 4, f = t & 15;
    const float invn = 1.0f / (float)Nn;
    float mu  = stat[f] * invn;
    float var = stat[16 + f] * invn - mu * mu;
    float v = (acc3[(node0 + nl) * 16 + f] - mu) * rsqrtf(var + BN_EPS) * g[f] + be[f];
    v = fmaxf(v, 0.f);
    sv[nl][f] = v;
    __syncthreads();
    if (t < 64) {
        int n2 = t >> 2, q = t & 3;
        __half2 p0 = __floats2half2_rn(sv[n2][q * 4 + 0], sv[n2][q * 4 + 1]);
        __half2 p1 = __floats2half2_rn(sv[n2][q * 4 + 2], sv[n2][q * 4 + 3]);
        uint2 u;
        u.x = *(unsigned*)&p0;
        u.y = *(unsigned*)&p1;
        g_h3h[(node0 + n2) * 4 + q] = u;
    }
    if (t < 128) {
        int n3 = t >> 3, h = t & 7;
        float s1 = 0.f, s2 = 0.f;
#pragma unroll
        for (int k = 0; k < 16; k++) {
            float hv = sv[n3][k];
            s1 += hv * sw[0][k][h];
            s2 += hv * sw[1][k][h];
        }
        g_as[(node0 + n3) * 8 + h] = s1;
        g_ad[(node0 + n3) * 8 + h] = s2;
    }
}

// ---------------- fused GAT (no-max softmax) + deg reset epilogue ----------------
__device__ __forceinline__ void gat_step(float l, uint2 u, float& sum, float4& acc) {
    float e = __expf(l);
    float2 f0 = __half22float2(*(const __half2*)&u.x);
    float2 f1 = __half22float2(*(const __half2*)&u.y);
    sum += e;
    acc.x += e * f0.x; acc.y += e * f0.y; acc.z += e * f1.x; acc.w += e * f1.y;
}

__global__ void k_gat(const float* __restrict__ Wg, const float* __restrict__ bg,
                      const int* __restrict__ batch) {
    __shared__ float Wgs[16 * 128];
    __shared__ float buf[8][8][16];     // [warp][head][k]
    for (int i = threadIdx.x; i < 16 * 128; i += blockDim.x) Wgs[i] = Wg[i];
    __syncthreads();
    int lane = threadIdx.x & 31, warp = threadIdx.x >> 5;
    int d = blockIdx.x * 8 + warp;      // grid = Nn/8 exact
    int h = lane >> 2, j = lane & 3;
    float adh = g_ad[d * 8 + h];
    int r0 = d * BUCKET, r1 = r0 + g_deg[d];

    float e0 = __expf(leaky(g_as[d * 8 + h] + adh));
    float sum = e0;
    uint2 su = __ldg(&g_h3h[d * 4 + j]);
    float2 sf0 = __half22float2(*(const __half2*)&su.x);
    float2 sf1 = __half22float2(*(const __half2*)&su.y);
    float4 acc = make_float4(e0 * sf0.x, e0 * sf0.y, e0 * sf1.x, e0 * sf1.y);

    int nb = (r1 - r0) >> 2;
    int k = r0 + (nb << 2);             // tail start
    if (nb >= 2) {
        int p0 = __ldg(&g_csrc[r0]),     p1 = __ldg(&g_csrc[r0 + 1]);
        int p2 = __ldg(&g_csrc[r0 + 2]), p3 = __ldg(&g_csrc[r0 + 3]);
        int q0 = __ldg(&g_csrc[r0 + 4]), q1 = __ldg(&g_csrc[r0 + 5]);
        int q2 = __ldg(&g_csrc[r0 + 6]), q3 = __ldg(&g_csrc[r0 + 7]);
        float la0 = __ldg(&g_as[p0 * 8 + h]), la1 = __ldg(&g_as[p1 * 8 + h]);
        float la2 = __ldg(&g_as[p2 * 8 + h]), la3 = __ldg(&g_as[p3 * 8 + h]);
        uint2 ua0 = __ldg(&g_h3h[p0 * 4 + j]);
        uint2 ua1 = __ldg(&g_h3h[p1 * 4 + j]);
        uint2 ua2 = __ldg(&g_h3h[p2 * 4 + j]);
        uint2 ua3 = __ldg(&g_h3h[p3 * 4 + j]);
        for (int t = 0; t < nb - 1; t++) {
            int c0, c1, c2, c3;
            bool more = (t + 2) < nb;
            if (more) {
                int base = r0 + (t + 2) * 4;
                c0 = __ldg(&g_csrc[base]);     c1 = __ldg(&g_csrc[base + 1]);
                c2 = __ldg(&g_csrc[base + 2]); c3 = __ldg(&g_csrc[base + 3]);
            }
            float lb0 = __ldg(&g_as[q0 * 8 + h]), lb1 = __ldg(&g_as[q1 * 8 + h]);
            float lb2 = __ldg(&g_as[q2 * 8 + h]), lb3 = __ldg(&g_as[q3 * 8 + h]);
            uint2 ub0 = __ldg(&g_h3h[q0 * 4 + j]);
            uint2 ub1 = __ldg(&g_h3h[q1 * 4 + j]);
            uint2 ub2 = __ldg(&g_h3h[q2 * 4 + j]);
            uint2 ub3 = __ldg(&g_h3h[q3 * 4 + j]);
            gat_step(leaky(la0 + adh), ua0, sum, acc);
            gat_step(leaky(la1 + adh), ua1, sum, acc);
            gat_step(leaky(la2 + adh), ua2, sum, acc);
            gat_step(leaky(la3 + adh), ua3, sum, acc);
            la0 = lb0; la1 = lb1; la2 = lb2; la3 = lb3;
            ua0 = ub0; ua1 = ub1; ua2 = ub2; ua3 = ub3;
            if (more) { q0 = c0; q1 = c1; q2 = c2; q3 = c3; }
        }
        gat_step(leaky(la0 + adh), ua0, sum, acc);
        gat_step(leaky(la1 + adh), ua1, sum, acc);
        gat_step(leaky(la2 + adh), ua2, sum, acc);
        gat_step(leaky(la3 + adh), ua3, sum, acc);
    } else if (nb == 1) {
        int p0 = __ldg(&g_csrc[r0]),     p1 = __ldg(&g_csrc[r0 + 1]);
        int p2 = __ldg(&g_csrc[r0 + 2]), p3 = __ldg(&g_csrc[r0 + 3]);
        float la0 = __ldg(&g_as[p0 * 8 + h]), la1 = __ldg(&g_as[p1 * 8 + h]);
        float la2 = __ldg(&g_as[p2 * 8 + h]), la3 = __ldg(&g_as[p3 * 8 + h]);
        uint2 ua0 = __ldg(&g_h3h[p0 * 4 + j]);
        uint2 ua1 = __ldg(&g_h3h[p1 * 4 + j]);
        uint2 ua2 = __ldg(&g_h3h[p2 * 4 + j]);
        uint2 ua3 = __ldg(&g_h3h[p3 * 4 + j]);
        gat_step(leaky(la0 + adh), ua0, sum, acc);
        gat_step(leaky(la1 + adh), ua1, sum, acc);
        gat_step(leaky(la2 + adh), ua2, sum, acc);
        gat_step(leaky(la3 + adh), ua3, sum, acc);
    }
    for (; k < r1; k++) {
        int s = __ldg(&g_csrc[k]);
        float l = leaky(__ldg(&g_as[s * 8 + h]) + adh);
        gat_step(l, __ldg(&g_h3h[s * 4 + j]), sum, acc);
    }
    float sc = 0.125f / sum;
    buf[warp][h][j * 4 + 0] = acc.x * sc;
    buf[warp][h][j * 4 + 1] = acc.y * sc;
    buf[warp][h][j * 4 + 2] = acc.z * sc;
    buf[warp][h][j * 4 + 3] = acc.w * sc;
    __syncwarp();

    if (lane == 0) g_deg[d] = 0;   // reset for next call

    if (lane < 4) {
        float4 hg = ((const float4*)bg)[lane];
#pragma unroll
        for (int hh = 0; hh < 8; hh++) {
#pragma unroll
            for (int kk = 0; kk < 16; kk++) {
                float a = buf[warp][hh][kk];
                const float4 w = *(const float4*)&Wgs[kk * 128 + hh * 16 + lane * 4];
                hg.x += a * w.x; hg.y += a * w.y; hg.z += a * w.z; hg.w += a * w.w;
            }
        }
        red4(((float4*)g_pool) + batch[d] * 4 + lane, hg);
    }
}

// one thread per graph: out[g] = pool[g]@Wf + bf, then zero its pool entries
__global__ void k_final(const float* __restrict__ Wf, const float* __restrict__ bf,
                        float* __restrict__ out) {
    int gg = blockIdx.x * blockDim.x + threadIdx.x;
    if (gg >= Gg) return;
    float p[16];
    float4* pp = (float4*)&g_pool[gg * 16];
#pragma unroll
    for (int q = 0; q < 4; q++) {
        float4 v = pp[q];
        p[q * 4 + 0] = v.x; p[q * 4 + 1] = v.y; p[q * 4 + 2] = v.z; p[q * 4 + 3] = v.w;
        pp[q] = make_float4(0.f, 0.f, 0.f, 0.f);
    }
#pragma unroll
    for (int k = 0; k < 3; k++) {
        float s = bf[k];
#pragma unroll
        for (int c = 0; c < 16; c++) s += p[c] * Wf[c * 3 + k];
        out[gg * 3 + k] = s;
    }
}

// ---------------- launch ----------------
static inline void* symaddr(const void* s) { void* p = nullptr; cudaGetSymbolAddress(&p, s); return p; }

extern "C" void kernel_launch(void* const* d_in, const int* in_sizes, int n_in,
                              void* d_out, int out_size) {
    const float* x       = (const float*)d_in[0];
    const int*   ei      = (const int*)  d_in[1];
    const int*   batch   = (const int*)  d_in[2];
    const float* W1 = (const float*)d_in[3],  *b1 = (const float*)d_in[4];
    const float* g1 = (const float*)d_in[5],  *be1= (const float*)d_in[6];
    const float* W2 = (const float*)d_in[7],  *b2 = (const float*)d_in[8];
    const float* g2 = (const float*)d_in[9],  *be2= (const float*)d_in[10];
    const float* W3 = (const float*)d_in[11], *b3 = (const float*)d_in[12];
    const float* g3 = (const float*)d_in[13], *be3= (const float*)d_in[14];
    const float* Wg = (const float*)d_in[15];
    const float* att_src = (const float*)d_in[16];
    const float* att_dst = (const float*)d_in[17];
    const float* bg = (const float*)d_in[18];
    const float* Wf = (const float*)d_in[19], *bf = (const float*)d_in[20];
    float* out = (float*)d_out;
    const int E = in_sizes[1] / 2;

    float* axp  = (float*)symaddr(g_axp);
    float* acc1 = (float*)symaddr(g_acc1);
    float* acc2 = (float*)symaddr(g_acc2);
    float* acc3 = (float*)symaddr(g_acc3);
    float* bn   = (float*)symaddr(g_bn);
    uint4* xh   = (uint4*)symaddr(g_xh);
    uint2* t2h  = (uint2*)symaddr(g_t2h);
    uint2* t3h  = (uint2*)symaddr(g_t3h);

    const int B = 256;
    // ---- bucket adjacency build ----
    k_fillb<<<(E / 8 + B) / B, B>>>(ei, E);
    k_dinvconvx<<<(Nn * 4 + B - 1) / B, B>>>(x);

    // ---- GCN layer 1: aggregate x' (half), vectorized GEMM 20->64 (+stats) ----
    k_gcn<4, false><<<(Nn + 63) / 64, B>>>(xh, nullptr, (float4*)axp, nullptr);
    k_gemm1<<<Nn / 16, B>>>(axp, W1, b1, (float4*)acc1, bn + 0);

    // ---- GCN layer 2: fused BN1+ReLU+GEMM 64->32 (*dinv, half), aggregate (+stats) ----
    k_gemmbn<64, 32><<<(Nn + 31) / 32, B>>>(acc1, bn + 0, g1, be1, W2, t2h);
    k_gcn<4, true><<<(Nn + 63) / 64, B>>>((const uint4*)t2h, b2, (float4*)acc2, bn + 128);

    // ---- GCN layer 3: fused BN2+ReLU+GEMM 32->16 (*dinv, half), aggregate (+stats) ----
    k_gemmbn<32, 16><<<(Nn + 63) / 64, B>>>(acc2, bn + 128, g2, be2, W3, t3h);
    k_gcn<2, true><<<(Nn + 127) / 128, B>>>((const uint4*)t3h, b3, (float4*)acc3, bn + 256);

    // ---- BN3 + attention dots fused, then no-max GAT (+deg reset) ----
    k_prep<<<1, 128>>>(Wg, att_src, att_dst);
    k_bn3att<<<Nn / 16, B>>>(acc3, bn + 256, g3, be3);
    k_gat<<<Nn / 8, B>>>(Wg, bg, batch);

    // ---- classifier (+pool reset) ----
    k_final<<<(Gg + B - 1) / B, B>>>(Wf, bf, out);
}

// round 16
// speedup vs baseline: 1.7373x; 1.3868x over previous
#include <cuda_runtime.h>
#include <cuda_fp16.h>

#define Nn 100000
#define MAXE 3200000
#define Gg 5000
#define BUCKET 96
#define BN_EPS 1e-5f

// ---------------- scratch (static device globals; zero-initialized at load) ----------------
__device__ int      g_deg [Nn];          // reset by k_gat epilogue each call
__device__ int      g_csrc[Nn * BUCKET]; // bucketed adjacency (src lists per dst)
__device__ float    g_dinv[Nn];
__device__ uint4    g_xh  [Nn * 4];     // x' = x*dinv, padded to 32 halfs
__device__ float    g_axp [Nn * 32];    // aggregated x', padded 32 floats
__device__ uint4    g_t2h [Nn * 4];     // t2' = bnrelu(acc1)@W2*dinv, 32 halfs
__device__ uint4    g_t3h [Nn * 2];     // t3' = bnrelu(acc2)@W3*dinv, 16 halfs
__device__ uint2    g_h3h [Nn * 4];     // h3 post-BN, 16 halfs
__device__ float    g_acc1[Nn * 64];
__device__ float    g_acc2[Nn * 32];
__device__ float    g_acc3[Nn * 16];
__device__ float    g_as  [Nn * 8];
__device__ float    g_ad  [Nn * 8];
__device__ float    g_was [16 * 8];
__device__ float    g_wad [16 * 8];
__device__ float    g_pool[Gg * 16];    // reset by k_final after reading
__device__ float    g_bn  [6 * 64];     // zeroed by k_fillb block 0 each call

// ---------------- helpers ----------------
__device__ __forceinline__ void red4(float4* p, float4 v) {
    asm volatile("red.global.add.v4.f32 [%0], {%1,%2,%3,%4};"
                 :: "l"(p), "f"(v.x), "f"(v.y), "f"(v.z), "f"(v.w) : "memory");
}
__device__ __forceinline__ float leaky(float v) { return v > 0.f ? v : 0.2f * v; }
__device__ __forceinline__ void acc8(float* a, uint4 u) {
    const __half2* h = (const __half2*)&u;
    float2 f0 = __half22float2(h[0]); a[0] += f0.x; a[1] += f0.y;
    float2 f1 = __half22float2(h[1]); a[2] += f1.x; a[3] += f1.y;
    float2 f2 = __half22float2(h[2]); a[4] += f2.x; a[5] += f2.y;
    float2 f3 = __half22float2(h[3]); a[6] += f3.x; a[7] += f3.y;
}
__device__ __forceinline__ uint4 hadd4(uint4 x, uint4 y) {
    uint4 r;
    asm("add.rn.f16x2 %0, %1, %2;" : "=r"(r.x) : "r"(x.x), "r"(y.x));
    asm("add.rn.f16x2 %0, %1, %2;" : "=r"(r.y) : "r"(x.y), "r"(y.y));
    asm("add.rn.f16x2 %0, %1, %2;" : "=r"(r.z) : "r"(x.z), "r"(y.z));
    asm("add.rn.f16x2 %0, %1, %2;" : "=r"(r.w) : "r"(x.w), "r"(y.w));
    return r;
}

// ---------------- single-pass bucket build ----------------
__global__ void k_fillb(const int* __restrict__ ei, int E) {
    if (blockIdx.x == 0) {
        for (int i = threadIdx.x; i < 6 * 64; i += blockDim.x) g_bn[i] = 0.f;
    }
    int t = blockIdx.x * blockDim.x + threadIdx.x;
    int i0 = t * 8;
    if (i0 + 7 < E) {
        int4 sa = *(const int4*)(ei + i0);
        int4 sb = *(const int4*)(ei + i0 + 4);
        int4 da = *(const int4*)(ei + E + i0);
        int4 db = *(const int4*)(ei + E + i0 + 4);
        int p0 = atomicAdd(&g_deg[da.x], 1);
        int p1 = atomicAdd(&g_deg[da.y], 1);
        int p2 = atomicAdd(&g_deg[da.z], 1);
        int p3 = atomicAdd(&g_deg[da.w], 1);
        int p4 = atomicAdd(&g_deg[db.x], 1);
        int p5 = atomicAdd(&g_deg[db.y], 1);
        int p6 = atomicAdd(&g_deg[db.z], 1);
        int p7 = atomicAdd(&g_deg[db.w], 1);
        g_csrc[da.x * BUCKET + p0] = sa.x;
        g_csrc[da.y * BUCKET + p1] = sa.y;
        g_csrc[da.z * BUCKET + p2] = sa.z;
        g_csrc[da.w * BUCKET + p3] = sa.w;
        g_csrc[db.x * BUCKET + p4] = sb.x;
        g_csrc[db.y * BUCKET + p5] = sb.y;
        g_csrc[db.z * BUCKET + p6] = sb.z;
        g_csrc[db.w * BUCKET + p7] = sb.w;
    } else {
        for (int i = i0; i < E; i++) {
            int d = ei[E + i];
            int p = atomicAdd(&g_deg[d], 1);
            g_csrc[d * BUCKET + p] = ei[i];
        }
    }
}

// dinv from deg + x' = x*dinv -> 32 halfs padded. Nn*4 threads.
__global__ void k_dinvconvx(const float* __restrict__ x) {
    int t = blockIdx.x * blockDim.x + threadIdx.x;
    if (t >= Nn * 4) return;
    int node = t >> 2, q = t & 3;
    float di = rsqrtf((float)(g_deg[node] + 1));   // +1 self loop
    if (q == 0) g_dinv[node] = di;
    __half hv[8];
#pragma unroll
    for (int k = 0; k < 8; k++) {
        int c = q * 8 + k;
        float v = (c < 20) ? x[node * 20 + c] * di : 0.f;
        hv[k] = __float2half_rn(v);
    }
    g_xh[node * 4 + q] = *(const uint4*)hv;
}

// ---------------- GCN bucket gather (half rows, dinv pre-folded, 2-stage pipeline) ----------------
template <int U4, bool STATS>
__global__ void __launch_bounds__(256, 4)
k_gcn(const uint4* __restrict__ rows, const float* __restrict__ b,
      float4* __restrict__ out4, float* __restrict__ stat) {
    const int F = U4 * 8;
    __shared__ float ss[F], sq[F];
    if (STATS) {
        if (threadIdx.x < F) { ss[threadIdx.x] = 0.f; sq[threadIdx.x] = 0.f; }
        __syncthreads();
    }
    const int GPW = 32 / U4;
    int lane = threadIdx.x & 31, warp = threadIdx.x >> 5;
    int grp = lane / U4, j = lane % U4;
    int node = (blockIdx.x * (blockDim.x >> 5) + warp) * GPW + grp;
    bool act = node < Nn;
    float a[8] = {0, 0, 0, 0, 0, 0, 0, 0};
    float di = 0.f;
    int r0 = 0, r1 = 0;
    if (act) {
        di = g_dinv[node];
        r0 = node * BUCKET;
        r1 = r0 + g_deg[node];
        acc8(a, __ldg(&rows[node * U4 + j]));  // self
    }
    int nb = (r1 - r0) >> 2;
    int k = r0 + (nb << 2);          // tail start
    if (nb >= 2) {
        int p0 = __ldg(&g_csrc[r0]),     p1 = __ldg(&g_csrc[r0 + 1]);
        int p2 = __ldg(&g_csrc[r0 + 2]), p3 = __ldg(&g_csrc[r0 + 3]);
        int q0 = __ldg(&g_csrc[r0 + 4]), q1 = __ldg(&g_csrc[r0 + 5]);
        int q2 = __ldg(&g_csrc[r0 + 6]), q3 = __ldg(&g_csrc[r0 + 7]);
        uint4 va0 = __ldg(&rows[p0 * U4 + j]);
        uint4 va1 = __ldg(&rows[p1 * U4 + j]);
        uint4 va2 = __ldg(&rows[p2 * U4 + j]);
        uint4 va3 = __ldg(&rows[p3 * U4 + j]);
        for (int t = 0; t < nb - 1; t++) {
            int c0, c1, c2, c3;
            bool more = (t + 2) < nb;
            if (more) {
                int base = r0 + (t + 2) * 4;
                c0 = __ldg(&g_csrc[base]);     c1 = __ldg(&g_csrc[base + 1]);
                c2 = __ldg(&g_csrc[base + 2]); c3 = __ldg(&g_csrc[base + 3]);
            }
            uint4 vb0 = __ldg(&rows[q0 * U4 + j]);
            uint4 vb1 = __ldg(&rows[q1 * U4 + j]);
            uint4 vb2 = __ldg(&rows[q2 * U4 + j]);
            uint4 vb3 = __ldg(&rows[q3 * U4 + j]);
            acc8(a, hadd4(va0, va1));
            acc8(a, hadd4(va2, va3));
            va0 = vb0; va1 = vb1; va2 = vb2; va3 = vb3;
            if (more) { q0 = c0; q1 = c1; q2 = c2; q3 = c3; }
        }
        acc8(a, hadd4(va0, va1));
        acc8(a, hadd4(va2, va3));
    } else if (nb == 1) {
        int p0 = __ldg(&g_csrc[r0]),     p1 = __ldg(&g_csrc[r0 + 1]);
        int p2 = __ldg(&g_csrc[r0 + 2]), p3 = __ldg(&g_csrc[r0 + 3]);
        uint4 va0 = __ldg(&rows[p0 * U4 + j]);
        uint4 va1 = __ldg(&rows[p1 * U4 + j]);
        uint4 va2 = __ldg(&rows[p2 * U4 + j]);
        uint4 va3 = __ldg(&rows[p3 * U4 + j]);
        acc8(a, hadd4(va0, va1));
        acc8(a, hadd4(va2, va3));
    }
    for (; k < r1; k++) acc8(a, __ldg(&rows[__ldg(&g_csrc[k]) * U4 + j]));

    float o[8];
    float4 b0 = b ? __ldg(&((const float4*)b)[j * 2])     : make_float4(0, 0, 0, 0);
    float4 b1 = b ? __ldg(&((const float4*)b)[j * 2 + 1]) : make_float4(0, 0, 0, 0);
#pragma unroll
    for (int c = 0; c < 8; c++) {
        float bb = (c < 4) ? (&b0.x)[c] : (&b1.x)[c - 4];
        o[c] = act ? (a[c] * di + bb) : 0.f;
    }
    if (act) {
        out4[node * (U4 * 2) + j * 2]     = make_float4(o[0], o[1], o[2], o[3]);
        out4[node * (U4 * 2) + j * 2 + 1] = make_float4(o[4], o[5], o[6], o[7]);
    }
    if (STATS) {
        float q[8];
#pragma unroll
        for (int c = 0; c < 8; c++) q[c] = o[c] * o[c];
#pragma unroll
        for (int off = U4; off < 32; off <<= 1) {
#pragma unroll
            for (int c = 0; c < 8; c++) {
                o[c] += __shfl_xor_sync(~0u, o[c], off);
                q[c] += __shfl_xor_sync(~0u, q[c], off);
            }
        }
        if (grp == 0) {
#pragma unroll
            for (int c = 0; c < 8; c++) {
                atomicAdd(&ss[j * 8 + c], o[c]);
                atomicAdd(&sq[j * 8 + c], q[c]);
            }
        }
        __syncthreads();
        if (threadIdx.x < F) {
            atomicAdd(&stat[threadIdx.x], ss[threadIdx.x]);
            atomicAdd(&stat[F + threadIdx.x], sq[threadIdx.x]);
        }
    }
}

// ---------------- GEMM layer 1: 2 nodes per thread (halved Ws LDS traffic) ----------------
// block 256 = 16 node-pairs x 16 fo4-groups -> 32 nodes/block. Nn % 32 == 0.
__global__ void k_gemm1(const float* __restrict__ h, const float* __restrict__ W,
                        const float* __restrict__ bias, float4* __restrict__ out,
                        float* __restrict__ stat) {
    __shared__ float4 Ws[20 * 16];
    __shared__ float Hs[32 * 36];
    __shared__ float ss[64], sq[64];
    int tid = threadIdx.x;
    for (int i = tid; i < 20 * 16; i += 256) Ws[i] = ((const float4*)W)[i];
    if (tid < 64) { ss[tid] = 0.f; sq[tid] = 0.f; }
    // stage 32 node rows (32 floats each, coalesced float4), padded stride 36
    {
        int r = tid >> 3, q = tid & 7;
        float4 v = ((const float4*)(h + (blockIdx.x * 32 + r) * 32))[q];
        *(float4*)&Hs[r * 36 + q * 4] = v;
    }
    __syncthreads();
    int np = tid >> 4, fo4 = tid & 15;
    int node0 = blockIdx.x * 32 + np * 2;       // Nn/32 = 3125 exact
    const float* h0 = &Hs[(np * 2) * 36];
    const float* h1 = h0 + 36;
    float4 bb = __ldg(&((const float4*)bias)[fo4]);
    float4 a0 = bb, a1 = bb;
#pragma unroll
    for (int fi = 0; fi < 20; fi++) {
        float4 w = Ws[fi * 16 + fo4];
        float x0 = h0[fi], x1 = h1[fi];
        a0.x += x0 * w.x; a0.y += x0 * w.y; a0.z += x0 * w.z; a0.w += x0 * w.w;
        a1.x += x1 * w.x; a1.y += x1 * w.y; a1.z += x1 * w.z; a1.w += x1 * w.w;
    }
    out[node0 * 16 + fo4] = a0;
    out[(node0 + 1) * 16 + fo4] = a1;
    // stats: local pair sum, then xor-16 combines the warp's other pair
    float4 s = make_float4(a0.x + a1.x, a0.y + a1.y, a0.z + a1.z, a0.w + a1.w);
    float4 s2 = make_float4(a0.x * a0.x + a1.x * a1.x, a0.y * a0.y + a1.y * a1.y,
                            a0.z * a0.z + a1.z * a1.z, a0.w * a0.w + a1.w * a1.w);
    s.x += __shfl_xor_sync(~0u, s.x, 16); s2.x += __shfl_xor_sync(~0u, s2.x, 16);
    s.y += __shfl_xor_sync(~0u, s.y, 16); s2.y += __shfl_xor_sync(~0u, s2.y, 16);
    s.z += __shfl_xor_sync(~0u, s.z, 16); s2.z += __shfl_xor_sync(~0u, s2.z, 16);
    s.w += __shfl_xor_sync(~0u, s.w, 16); s2.w += __shfl_xor_sync(~0u, s2.w, 16);
    if ((tid & 31) < 16) {
        atomicAdd(&ss[fo4 * 4 + 0], s.x); atomicAdd(&sq[fo4 * 4 + 0], s2.x);
        atomicAdd(&ss[fo4 * 4 + 1], s.y); atomicAdd(&sq[fo4 * 4 + 1], s2.y);
        atomicAdd(&ss[fo4 * 4 + 2], s.z); atomicAdd(&sq[fo4 * 4 + 2], s2.z);
        atomicAdd(&ss[fo4 * 4 + 3], s.w); atomicAdd(&sq[fo4 * 4 + 3], s2.w);
    }
    __syncthreads();
    if (tid < 64) {
        atomicAdd(&stat[tid], ss[tid]);
        atomicAdd(&stat[64 + tid], sq[tid]);
    }
}

// ---------------- fused BN+ReLU + GEMM + *dinv -> half (2 nodes per thread) ----------------
// block 256, NODES = 2*(256/G4) nodes per block.
template <int FI, int FO>
__global__ void k_gemmbn(const float* __restrict__ acc, const float* __restrict__ stat,
                         const float* __restrict__ g, const float* __restrict__ be,
                         const float* __restrict__ W, uint2* __restrict__ out) {
    const int G4 = FO / 4;
    const int NODES = 2 * (256 / G4);
    const int HP = FI + 4;
    __shared__ float4 Ws[FI * G4];
    __shared__ float Hs[NODES * HP];
    __shared__ float sc[FI], sh[FI];
    int tid = threadIdx.x;
    for (int i = tid; i < FI * G4; i += 256) Ws[i] = ((const float4*)W)[i];
    if (tid < FI) {
        const float invn = 1.0f / (float)Nn;
        float mu  = stat[tid] * invn;
        float var = stat[FI + tid] * invn - mu * mu;
        float kk  = g[tid] * rsqrtf(var + BN_EPS);
        sc[tid] = kk;
        sh[tid] = be[tid] - mu * kk;
    }
    __syncthreads();
    int node0 = blockIdx.x * NODES;
    int nv = Nn - node0; if (nv > NODES) nv = NODES;   // nv stays even (Nn%32==0)
    for (int i = tid; i < nv * (FI / 4); i += 256) {
        int r = i / (FI / 4), q = i % (FI / 4);
        float4 v = ((const float4*)(acc + (node0 + r) * FI))[q];
        int f = q * 4;
        v.x = fmaxf(v.x * sc[f + 0] + sh[f + 0], 0.f);
        v.y = fmaxf(v.y * sc[f + 1] + sh[f + 1], 0.f);
        v.z = fmaxf(v.z * sc[f + 2] + sh[f + 2], 0.f);
        v.w = fmaxf(v.w * sc[f + 3] + sh[f + 3], 0.f);
        *(float4*)&Hs[r * HP + f] = v;
    }
    __syncthreads();
    int np = tid / G4, fo4 = tid % G4;
    int nl0 = np * 2;
    if (nl0 >= nv) return;
    int node = node0 + nl0;
    const float* h0 = &Hs[nl0 * HP];
    const float* h1 = h0 + HP;
    float4 a0 = make_float4(0.f, 0.f, 0.f, 0.f);
    float4 a1 = make_float4(0.f, 0.f, 0.f, 0.f);
#pragma unroll
    for (int fi = 0; fi < FI; fi++) {
        float4 w = Ws[fi * G4 + fo4];
        float x0 = h0[fi], x1 = h1[fi];
        a0.x += x0 * w.x; a0.y += x0 * w.y; a0.z += x0 * w.z; a0.w += x0 * w.w;
        a1.x += x1 * w.x; a1.y += x1 * w.y; a1.z += x1 * w.z; a1.w += x1 * w.w;
    }
    float d0 = g_dinv[node], d1 = g_dinv[node + 1];
    a0.x *= d0; a0.y *= d0; a0.z *= d0; a0.w *= d0;
    a1.x *= d1; a1.y *= d1; a1.z *= d1; a1.w *= d1;
    __half2 h00 = __floats2half2_rn(a0.x, a0.y), h01 = __floats2half2_rn(a0.z, a0.w);
    __half2 h10 = __floats2half2_rn(a1.x, a1.y), h11 = __floats2half2_rn(a1.z, a1.w);
    uint2 u0, u1;
    u0.x = *(unsigned*)&h00; u0.y = *(unsigned*)&h01;
    u1.x = *(unsigned*)&h10; u1.y = *(unsigned*)&h11;
    out[node * G4 + fo4] = u0;
    out[(node + 1) * G4 + fo4] = u1;
}

// was[k][h] = sum_c Wg[k][h*16+c]*att_src[h][c]; wad likewise. 128 threads.
__global__ void k_prep(const float* __restrict__ Wg, const float* __restrict__ asrc,
                       const float* __restrict__ adst) {
    int t = threadIdx.x;
    int k = t >> 3, h = t & 7;
    float s1 = 0.f, s2 = 0.f;
#pragma unroll
    for (int c = 0; c < 16; c++) {
        float w = Wg[k * 128 + h * 16 + c];
        s1 += w * asrc[h * 16 + c];
        s2 += w * adst[h * 16 + c];
    }
    g_was[k * 8 + h] = s1;
    g_wad[k * 8 + h] = s2;
}

// fused BN+ReLU(layer3) + h3->half + attention dots. block=256 -> 16 nodes. Nn%16==0.
__global__ void k_bn3att(const float* __restrict__ acc3, const float* __restrict__ stat,
                         const float* __restrict__ g, const float* __restrict__ be) {
    __shared__ float sv[16][17];
    __shared__ float sw[2][16][8];
    int t = threadIdx.x;
    if (t < 128) { sw[0][t >> 3][t & 7] = g_was[t]; sw[1][t >> 3][t & 7] = g_wad[t]; }
    int node0 = blockIdx.x * 16;
    int nl = t >> 4, f = t & 15;
    const float invn = 1.0f / (float)Nn;
    float mu  = stat[f] * invn;
    float var = stat[16 + f] * invn - mu * mu;
    float v = (acc3[(node0 + nl) * 16 + f] - mu) * rsqrtf(var + BN_EPS) * g[f] + be[f];
    v = fmaxf(v, 0.f);
    sv[nl][f] = v;
    __syncthreads();
    if (t < 64) {
        int n2 = t >> 2, q = t & 3;
        __half2 p0 = __floats2half2_rn(sv[n2][q * 4 + 0], sv[n2][q * 4 + 1]);
        __half2 p1 = __floats2half2_rn(sv[n2][q * 4 + 2], sv[n2][q * 4 + 3]);
        uint2 u;
        u.x = *(unsigned*)&p0;
        u.y = *(unsigned*)&p1;
        g_h3h[(node0 + n2) * 4 + q] = u;
    }
    if (t < 128) {
        int n3 = t >> 3, h = t & 7;
        float s1 = 0.f, s2 = 0.f;
#pragma unroll
        for (int k = 0; k < 16; k++) {
            float hv = sv[n3][k];
            s1 += hv * sw[0][k][h];
            s2 += hv * sw[1][k][h];
        }
        g_as[(node0 + n3) * 8 + h] = s1;
        g_ad[(node0 + n3) * 8 + h] = s2;
    }
}

// ---------------- fused GAT (no-max softmax) + full-warp epilogue + deg reset ----------------
__device__ __forceinline__ void gat_step(float l, uint2 u, float& sum, float4& acc) {
    float e = __expf(l);
    float2 f0 = __half22float2(*(const __half2*)&u.x);
    float2 f1 = __half22float2(*(const __half2*)&u.y);
    sum += e;
    acc.x += e * f0.x; acc.y += e * f0.y; acc.z += e * f1.x; acc.w += e * f1.y;
}

__global__ void k_gat(const float* __restrict__ Wg, const float* __restrict__ bg,
                      const int* __restrict__ batch) {
    __shared__ float Wgs[16 * 128];
    __shared__ float buf[8][8][16];     // [warp][head][k]
    for (int i = threadIdx.x; i < 16 * 128; i += blockDim.x) Wgs[i] = Wg[i];
    __syncthreads();
    int lane = threadIdx.x & 31, warp = threadIdx.x >> 5;
    int d = blockIdx.x * 8 + warp;      // grid = Nn/8 exact
    int h = lane >> 2, j = lane & 3;
    float adh = g_ad[d * 8 + h];
    int r0 = d * BUCKET, r1 = r0 + g_deg[d];

    float e0 = __expf(leaky(g_as[d * 8 + h] + adh));
    float sum = e0;
    uint2 su = __ldg(&g_h3h[d * 4 + j]);
    float2 sf0 = __half22float2(*(const __half2*)&su.x);
    float2 sf1 = __half22float2(*(const __half2*)&su.y);
    float4 acc = make_float4(e0 * sf0.x, e0 * sf0.y, e0 * sf1.x, e0 * sf1.y);

    int nb = (r1 - r0) >> 2;
    int k = r0 + (nb << 2);             // tail start
    if (nb >= 2) {
        int p0 = __ldg(&g_csrc[r0]),     p1 = __ldg(&g_csrc[r0 + 1]);
        int p2 = __ldg(&g_csrc[r0 + 2]), p3 = __ldg(&g_csrc[r0 + 3]);
        int q0 = __ldg(&g_csrc[r0 + 4]), q1 = __ldg(&g_csrc[r0 + 5]);
        int q2 = __ldg(&g_csrc[r0 + 6]), q3 = __ldg(&g_csrc[r0 + 7]);
        float la0 = __ldg(&g_as[p0 * 8 + h]), la1 = __ldg(&g_as[p1 * 8 + h]);
        float la2 = __ldg(&g_as[p2 * 8 + h]), la3 = __ldg(&g_as[p3 * 8 + h]);
        uint2 ua0 = __ldg(&g_h3h[p0 * 4 + j]);
        uint2 ua1 = __ldg(&g_h3h[p1 * 4 + j]);
        uint2 ua2 = __ldg(&g_h3h[p2 * 4 + j]);
        uint2 ua3 = __ldg(&g_h3h[p3 * 4 + j]);
        for (int t = 0; t < nb - 1; t++) {
            int c0, c1, c2, c3;
            bool more = (t + 2) < nb;
            if (more) {
                int base = r0 + (t + 2) * 4;
                c0 = __ldg(&g_csrc[base]);     c1 = __ldg(&g_csrc[base + 1]);
                c2 = __ldg(&g_csrc[base + 2]); c3 = __ldg(&g_csrc[base + 3]);
            }
            float lb0 = __ldg(&g_as[q0 * 8 + h]), lb1 = __ldg(&g_as[q1 * 8 + h]);
            float lb2 = __ldg(&g_as[q2 * 8 + h]), lb3 = __ldg(&g_as[q3 * 8 + h]);
            uint2 ub0 = __ldg(&g_h3h[q0 * 4 + j]);
            uint2 ub1 = __ldg(&g_h3h[q1 * 4 + j]);
            uint2 ub2 = __ldg(&g_h3h[q2 * 4 + j]);
            uint2 ub3 = __ldg(&g_h3h[q3 * 4 + j]);
            gat_step(leaky(la0 + adh), ua0, sum, acc);
            gat_step(leaky(la1 + adh), ua1, sum, acc);
            gat_step(leaky(la2 + adh), ua2, sum, acc);
            gat_step(leaky(la3 + adh), ua3, sum, acc);
            la0 = lb0; la1 = lb1; la2 = lb2; la3 = lb3;
            ua0 = ub0; ua1 = ub1; ua2 = ub2; ua3 = ub3;
            if (more) { q0 = c0; q1 = c1; q2 = c2; q3 = c3; }
        }
        gat_step(leaky(la0 + adh), ua0, sum, acc);
        gat_step(leaky(la1 + adh), ua1, sum, acc);
        gat_step(leaky(la2 + adh), ua2, sum, acc);
        gat_step(leaky(la3 + adh), ua3, sum, acc);
    } else if (nb == 1) {
        int p0 = __ldg(&g_csrc[r0]),     p1 = __ldg(&g_csrc[r0 + 1]);
        int p2 = __ldg(&g_csrc[r0 + 2]), p3 = __ldg(&g_csrc[r0 + 3]);
        float la0 = __ldg(&g_as[p0 * 8 + h]), la1 = __ldg(&g_as[p1 * 8 + h]);
        float la2 = __ldg(&g_as[p2 * 8 + h]), la3 = __ldg(&g_as[p3 * 8 + h]);
        uint2 ua0 = __ldg(&g_h3h[p0 * 4 + j]);
        uint2 ua1 = __ldg(&g_h3h[p1 * 4 + j]);
        uint2 ua2 = __ldg(&g_h3h[p2 * 4 + j]);
        uint2 ua3 = __ldg(&g_h3h[p3 * 4 + j]);
        gat_step(leaky(la0 + adh), ua0, sum, acc);
        gat_step(leaky(la1 + adh), ua1, sum, acc);
        gat_step(leaky(la2 + adh), ua2, sum, acc);
        gat_step(leaky(la3 + adh), ua3, sum, acc);
    }
    for (; k < r1; k++) {
        int s = __ldg(&g_csrc[k]);
        float l = leaky(__ldg(&g_as[s * 8 + h]) + adh);
        gat_step(l, __ldg(&g_h3h[s * 4 + j]), sum, acc);
    }
    float sc = 0.125f / sum;
    buf[warp][h][j * 4 + 0] = acc.x * sc;
    buf[warp][h][j * 4 + 1] = acc.y * sc;
    buf[warp][h][j * 4 + 2] = acc.z * sc;
    buf[warp][h][j * 4 + 3] = acc.w * sc;
    __syncwarp();

    if (lane == 0) g_deg[d] = 0;   // reset for next call

    // full-warp mini-GEMM: lane = (c, k-half); hg[c] = bg[c] + sum_hh sum_kk buf[hh][kk]*Wg[kk][hh*16+c]
    int c = lane & 15, hf = lane >> 4;
    float s = 0.f;
#pragma unroll
    for (int hh = 0; hh < 8; hh++) {
#pragma unroll
        for (int kq = 0; kq < 8; kq++) {
            int kk = hf * 8 + kq;
            s += buf[warp][hh][kk] * Wgs[kk * 128 + hh * 16 + c];
        }
    }
    s += __shfl_xor_sync(~0u, s, 16);
    __syncwarp();
    if (lane < 16) buf[warp][0][c] = s + bg[c];
    __syncwarp();
    if (lane < 4) {
        float4 hg = *(const float4*)&buf[warp][0][lane * 4];
        red4(((float4*)g_pool) + batch[d] * 4 + lane, hg);
    }
}

// one thread per graph: out[g] = pool[g]@Wf + bf, then zero its pool entries
__global__ void k_final(const float* __restrict__ Wf, const float* __restrict__ bf,
                        float* __restrict__ out) {
    int gg = blockIdx.x * blockDim.x + threadIdx.x;
    if (gg >= Gg) return;
    float p[16];
    float4* pp = (float4*)&g_pool[gg * 16];
#pragma unroll
    for (int q = 0; q < 4; q++) {
        float4 v = pp[q];
        p[q * 4 + 0] = v.x; p[q * 4 + 1] = v.y; p[q * 4 + 2] = v.z; p[q * 4 + 3] = v.w;
        pp[q] = make_float4(0.f, 0.f, 0.f, 0.f);
    }
#pragma unroll
    for (int k = 0; k < 3; k++) {
        float s = bf[k];
#pragma unroll
        for (int c = 0; c < 16; c++) s += p[c] * Wf[c * 3 + k];
        out[gg * 3 + k] = s;
    }
}

// ---------------- launch ----------------
static inline void* symaddr(const void* s) { void* p = nullptr; cudaGetSymbolAddress(&p, s); return p; }

extern "C" void kernel_launch(void* const* d_in, const int* in_sizes, int n_in,
                              void* d_out, int out_size) {
    const float* x       = (const float*)d_in[0];
    const int*   ei      = (const int*)  d_in[1];
    const int*   batch   = (const int*)  d_in[2];
    const float* W1 = (const float*)d_in[3],  *b1 = (const float*)d_in[4];
    const float* g1 = (const float*)d_in[5],  *be1= (const float*)d_in[6];
    const float* W2 = (const float*)d_in[7],  *b2 = (const float*)d_in[8];
    const float* g2 = (const float*)d_in[9],  *be2= (const float*)d_in[10];
    const float* W3 = (const float*)d_in[11], *b3 = (const float*)d_in[12];
    const float* g3 = (const float*)d_in[13], *be3= (const float*)d_in[14];
    const float* Wg = (const float*)d_in[15];
    const float* att_src = (const float*)d_in[16];
    const float* att_dst = (const float*)d_in[17];
    const float* bg = (const float*)d_in[18];
    const float* Wf = (const float*)d_in[19], *bf = (const float*)d_in[20];
    float* out = (float*)d_out;
    const int E = in_sizes[1] / 2;

    float* axp  = (float*)symaddr(g_axp);
    float* acc1 = (float*)symaddr(g_acc1);
    float* acc2 = (float*)symaddr(g_acc2);
    float* acc3 = (float*)symaddr(g_acc3);
    float* bn   = (float*)symaddr(g_bn);
    uint4* xh   = (uint4*)symaddr(g_xh);
    uint2* t2h  = (uint2*)symaddr(g_t2h);
    uint2* t3h  = (uint2*)symaddr(g_t3h);

    const int B = 256;
    // ---- bucket adjacency build ----
    k_fillb<<<(E / 8 + B) / B, B>>>(ei, E);
    k_dinvconvx<<<(Nn * 4 + B - 1) / B, B>>>(x);

    // ---- GCN layer 1: aggregate x' (half), vectorized GEMM 20->64 (+stats) ----
    k_gcn<4, false><<<(Nn + 63) / 64, B>>>(xh, nullptr, (float4*)axp, nullptr);
    k_gemm1<<<Nn / 32, B>>>(axp, W1, b1, (float4*)acc1, bn + 0);

    // ---- GCN layer 2: fused BN1+ReLU+GEMM 64->32 (*dinv, half), aggregate (+stats) ----
    k_gemmbn<64, 32><<<(Nn + 63) / 64, B>>>(acc1, bn + 0, g1, be1, W2, t2h);
    k_gcn<4, true><<<(Nn + 63) / 64, B>>>((const uint4*)t2h, b2, (float4*)acc2, bn + 128);

    // ---- GCN layer 3: fused BN2+ReLU+GEMM 32->16 (*dinv, half), aggregate (+stats) ----
    k_gemmbn<32, 16><<<(Nn + 127) / 128, B>>>(acc2, bn + 128, g2, be2, W3, t3h);
    k_gcn<2, true><<<(Nn + 127) / 128, B>>>((const uint4*)t3h, b3, (float4*)acc3, bn + 256);

    // ---- BN3 + attention dots fused, then no-max GAT (+deg reset) ----
    k_prep<<<1, 128>>>(Wg, att_src, att_dst);
    k_bn3att<<<Nn / 16, B>>>(acc3, bn + 256, g3, be3);
    k_gat<<<Nn / 8, B>>>(Wg, bg, batch);

    // ---- classifier (+pool reset) ----
    k_final<<<(Gg + B - 1) / B, B>>>(Wf, bf, out);
}

// round 17
// speedup vs baseline: 1.7802x; 1.0247x over previous
#include <cuda_runtime.h>
#include <cuda_fp16.h>

#define Nn 100000
#define MAXE 3200000
#define Gg 5000
#define BUCKET 96
#define BN_EPS 1e-5f

// ---------------- scratch (static device globals; zero-initialized at load) ----------------
__device__ int      g_deg [Nn];          // reset by k_gat epilogue each call
__device__ int      g_csrc[Nn * BUCKET]; // bucketed adjacency (src lists per dst)
__device__ float    g_dinv[Nn];
__device__ uint4    g_xh  [Nn * 4];     // x' = x*dinv, padded to 32 halfs
__device__ float    g_axp [Nn * 32];    // aggregated x', padded 32 floats
__device__ uint4    g_t2h [Nn * 4];     // t2' = bnrelu(acc1)@W2*dinv, 32 halfs
__device__ uint4    g_t3h [Nn * 2];     // t3' = bnrelu(acc2)@W3*dinv, 16 halfs
__device__ uint2    g_h3h [Nn * 4];     // h3 post-BN, 16 halfs
__device__ float    g_acc1[Nn * 64];
__device__ float    g_acc2[Nn * 32];
__device__ float    g_acc3[Nn * 16];
__device__ float    g_as  [Nn * 8];
__device__ float    g_ad  [Nn * 8];
__device__ float    g_was [16 * 8];
__device__ float    g_wad [16 * 8];
__device__ float    g_pool[Gg * 16];    // reset by k_final after reading
__device__ float    g_bn  [6 * 64];     // zeroed by k_fillb block 0 each call

// ---------------- helpers ----------------
__device__ __forceinline__ void red4(float4* p, float4 v) {
    asm volatile("red.global.add.v4.f32 [%0], {%1,%2,%3,%4};"
                 :: "l"(p), "f"(v.x), "f"(v.y), "f"(v.z), "f"(v.w) : "memory");
}
__device__ __forceinline__ float leaky(float v) { return v > 0.f ? v : 0.2f * v; }
__device__ __forceinline__ void acc8(float* a, uint4 u) {
    const __half2* h = (const __half2*)&u;
    float2 f0 = __half22float2(h[0]); a[0] += f0.x; a[1] += f0.y;
    float2 f1 = __half22float2(h[1]); a[2] += f1.x; a[3] += f1.y;
    float2 f2 = __half22float2(h[2]); a[4] += f2.x; a[5] += f2.y;
    float2 f3 = __half22float2(h[3]); a[6] += f3.x; a[7] += f3.y;
}
__device__ __forceinline__ uint4 hadd4(uint4 x, uint4 y) {
    uint4 r;
    asm("add.rn.f16x2 %0, %1, %2;" : "=r"(r.x) : "r"(x.x), "r"(y.x));
    asm("add.rn.f16x2 %0, %1, %2;" : "=r"(r.y) : "r"(x.y), "r"(y.y));
    asm("add.rn.f16x2 %0, %1, %2;" : "=r"(r.z) : "r"(x.z), "r"(y.z));
    asm("add.rn.f16x2 %0, %1, %2;" : "=r"(r.w) : "r"(x.w), "r"(y.w));
    return r;
}

// ---------------- single-pass bucket build ----------------
__global__ void k_fillb(const int* __restrict__ ei, int E) {
    if (blockIdx.x == 0) {
        for (int i = threadIdx.x; i < 6 * 64; i += blockDim.x) g_bn[i] = 0.f;
    }
    int t = blockIdx.x * blockDim.x + threadIdx.x;
    int i0 = t * 8;
    if (i0 + 7 < E) {
        int4 sa = *(const int4*)(ei + i0);
        int4 sb = *(const int4*)(ei + i0 + 4);
        int4 da = *(const int4*)(ei + E + i0);
        int4 db = *(const int4*)(ei + E + i0 + 4);
        int p0 = atomicAdd(&g_deg[da.x], 1);
        int p1 = atomicAdd(&g_deg[da.y], 1);
        int p2 = atomicAdd(&g_deg[da.z], 1);
        int p3 = atomicAdd(&g_deg[da.w], 1);
        int p4 = atomicAdd(&g_deg[db.x], 1);
        int p5 = atomicAdd(&g_deg[db.y], 1);
        int p6 = atomicAdd(&g_deg[db.z], 1);
        int p7 = atomicAdd(&g_deg[db.w], 1);
        g_csrc[da.x * BUCKET + p0] = sa.x;
        g_csrc[da.y * BUCKET + p1] = sa.y;
        g_csrc[da.z * BUCKET + p2] = sa.z;
        g_csrc[da.w * BUCKET + p3] = sa.w;
        g_csrc[db.x * BUCKET + p4] = sb.x;
        g_csrc[db.y * BUCKET + p5] = sb.y;
        g_csrc[db.z * BUCKET + p6] = sb.z;
        g_csrc[db.w * BUCKET + p7] = sb.w;
    } else {
        for (int i = i0; i < E; i++) {
            int d = ei[E + i];
            int p = atomicAdd(&g_deg[d], 1);
            g_csrc[d * BUCKET + p] = ei[i];
        }
    }
}

// dinv from deg + x' = x*dinv -> 32 halfs padded. Nn*4 threads.
__global__ void k_dinvconvx(const float* __restrict__ x) {
    int t = blockIdx.x * blockDim.x + threadIdx.x;
    if (t >= Nn * 4) return;
    int node = t >> 2, q = t & 3;
    float di = rsqrtf((float)(g_deg[node] + 1));   // +1 self loop
    if (q == 0) g_dinv[node] = di;
    __half hv[8];
#pragma unroll
    for (int k = 0; k < 8; k++) {
        int c = q * 8 + k;
        float v = (c < 20) ? x[node * 20 + c] * di : 0.f;
        hv[k] = __float2half_rn(v);
    }
    g_xh[node * 4 + q] = *(const uint4*)hv;
}

// ---------------- GCN bucket gather (half rows, dinv pre-folded, 2-stage pipeline) ----------------
template <int U4, bool STATS>
__global__ void __launch_bounds__(256, 4)
k_gcn(const uint4* __restrict__ rows, const float* __restrict__ b,
      float4* __restrict__ out4, float* __restrict__ stat) {
    const int F = U4 * 8;
    __shared__ float ss[F], sq[F];
    if (STATS) {
        if (threadIdx.x < F) { ss[threadIdx.x] = 0.f; sq[threadIdx.x] = 0.f; }
        __syncthreads();
    }
    const int GPW = 32 / U4;
    int lane = threadIdx.x & 31, warp = threadIdx.x >> 5;
    int grp = lane / U4, j = lane % U4;
    int node = (blockIdx.x * (blockDim.x >> 5) + warp) * GPW + grp;
    bool act = node < Nn;
    float a[8] = {0, 0, 0, 0, 0, 0, 0, 0};
    float di = 0.f;
    int r0 = 0, r1 = 0;
    if (act) {
        di = g_dinv[node];
        r0 = node * BUCKET;
        r1 = r0 + g_deg[node];
        acc8(a, __ldg(&rows[node * U4 + j]));  // self
    }
    int nb = (r1 - r0) >> 2;
    int k = r0 + (nb << 2);          // tail start
    if (nb >= 2) {
        int p0 = __ldg(&g_csrc[r0]),     p1 = __ldg(&g_csrc[r0 + 1]);
        int p2 = __ldg(&g_csrc[r0 + 2]), p3 = __ldg(&g_csrc[r0 + 3]);
        int q0 = __ldg(&g_csrc[r0 + 4]), q1 = __ldg(&g_csrc[r0 + 5]);
        int q2 = __ldg(&g_csrc[r0 + 6]), q3 = __ldg(&g_csrc[r0 + 7]);
        uint4 va0 = __ldg(&rows[p0 * U4 + j]);
        uint4 va1 = __ldg(&rows[p1 * U4 + j]);
        uint4 va2 = __ldg(&rows[p2 * U4 + j]);
        uint4 va3 = __ldg(&rows[p3 * U4 + j]);
        for (int t = 0; t < nb - 1; t++) {
            int c0, c1, c2, c3;
            bool more = (t + 2) < nb;
            if (more) {
                int base = r0 + (t + 2) * 4;
                c0 = __ldg(&g_csrc[base]);     c1 = __ldg(&g_csrc[base + 1]);
                c2 = __ldg(&g_csrc[base + 2]); c3 = __ldg(&g_csrc[base + 3]);
            }
            uint4 vb0 = __ldg(&rows[q0 * U4 + j]);
            uint4 vb1 = __ldg(&rows[q1 * U4 + j]);
            uint4 vb2 = __ldg(&rows[q2 * U4 + j]);
            uint4 vb3 = __ldg(&rows[q3 * U4 + j]);
            acc8(a, hadd4(va0, va1));
            acc8(a, hadd4(va2, va3));
            va0 = vb0; va1 = vb1; va2 = vb2; va3 = vb3;
            if (more) { q0 = c0; q1 = c1; q2 = c2; q3 = c3; }
        }
        acc8(a, hadd4(va0, va1));
        acc8(a, hadd4(va2, va3));
    } else if (nb == 1) {
        int p0 = __ldg(&g_csrc[r0]),     p1 = __ldg(&g_csrc[r0 + 1]);
        int p2 = __ldg(&g_csrc[r0 + 2]), p3 = __ldg(&g_csrc[r0 + 3]);
        uint4 va0 = __ldg(&rows[p0 * U4 + j]);
        uint4 va1 = __ldg(&rows[p1 * U4 + j]);
        uint4 va2 = __ldg(&rows[p2 * U4 + j]);
        uint4 va3 = __ldg(&rows[p3 * U4 + j]);
        acc8(a, hadd4(va0, va1));
        acc8(a, hadd4(va2, va3));
    }
    for (; k < r1; k++) acc8(a, __ldg(&rows[__ldg(&g_csrc[k]) * U4 + j]));

    float o[8];
    float4 b0 = b ? __ldg(&((const float4*)b)[j * 2])     : make_float4(0, 0, 0, 0);
    float4 b1 = b ? __ldg(&((const float4*)b)[j * 2 + 1]) : make_float4(0, 0, 0, 0);
#pragma unroll
    for (int c = 0; c < 8; c++) {
        float bb = (c < 4) ? (&b0.x)[c] : (&b1.x)[c - 4];
        o[c] = act ? (a[c] * di + bb) : 0.f;
    }
    if (act) {
        out4[node * (U4 * 2) + j * 2]     = make_float4(o[0], o[1], o[2], o[3]);
        out4[node * (U4 * 2) + j * 2 + 1] = make_float4(o[4], o[5], o[6], o[7]);
    }
    if (STATS) {
        float q[8];
#pragma unroll
        for (int c = 0; c < 8; c++) q[c] = o[c] * o[c];
#pragma unroll
        for (int off = U4; off < 32; off <<= 1) {
#pragma unroll
            for (int c = 0; c < 8; c++) {
                o[c] += __shfl_xor_sync(~0u, o[c], off);
                q[c] += __shfl_xor_sync(~0u, q[c], off);
            }
        }
        if (grp == 0) {
#pragma unroll
            for (int c = 0; c < 8; c++) {
                atomicAdd(&ss[j * 8 + c], o[c]);
                atomicAdd(&sq[j * 8 + c], q[c]);
            }
        }
        __syncthreads();
        if (threadIdx.x < F) {
            atomicAdd(&stat[threadIdx.x], ss[threadIdx.x]);
            atomicAdd(&stat[F + threadIdx.x], sq[threadIdx.x]);
        }
    }
}

// ---------------- GEMM layer 1: 4 nodes per thread ----------------
// block 256 = 16 node-quads x 16 fo4-groups -> 64 nodes/block. nv is a multiple of 32.
__global__ void k_gemm1(const float* __restrict__ h, const float* __restrict__ W,
                        const float* __restrict__ bias, float4* __restrict__ out,
                        float* __restrict__ stat) {
    __shared__ float4 Ws[20 * 16];
    __shared__ float Hs[64 * 36];
    __shared__ float ss[64], sq[64];
    int tid = threadIdx.x;
    for (int i = tid; i < 20 * 16; i += 256) Ws[i] = ((const float4*)W)[i];
    if (tid < 64) { ss[tid] = 0.f; sq[tid] = 0.f; }
    int node0b = blockIdx.x * 64;
    int nv = Nn - node0b; if (nv > 64) nv = 64;        // 64 or 32
    for (int i = tid; i < nv * 8; i += 256) {
        int r = i >> 3, q = i & 7;
        float4 v = ((const float4*)(h + (node0b + r) * 32))[q];
        *(float4*)&Hs[r * 36 + q * 4] = v;
    }
    __syncthreads();
    int np = tid >> 4, fo4 = tid & 15;
    int nl0 = np * 4;
    float4 bb = __ldg(&((const float4*)bias)[fo4]);
    float4 a0 = bb, a1 = bb, a2 = bb, a3 = bb;
    bool act = nl0 < nv;
    if (act) {
        const float* h0 = &Hs[nl0 * 36];
#pragma unroll
        for (int fi = 0; fi < 20; fi++) {
            float4 w = Ws[fi * 16 + fo4];
            float x0 = h0[fi], x1 = h0[36 + fi], x2 = h0[72 + fi], x3 = h0[108 + fi];
            a0.x += x0 * w.x; a0.y += x0 * w.y; a0.z += x0 * w.z; a0.w += x0 * w.w;
            a1.x += x1 * w.x; a1.y += x1 * w.y; a1.z += x1 * w.z; a1.w += x1 * w.w;
            a2.x += x2 * w.x; a2.y += x2 * w.y; a2.z += x2 * w.z; a2.w += x2 * w.w;
            a3.x += x3 * w.x; a3.y += x3 * w.y; a3.z += x3 * w.z; a3.w += x3 * w.w;
        }
        int node = node0b + nl0;
        out[node * 16 + fo4]       = a0;
        out[(node + 1) * 16 + fo4] = a1;
        out[(node + 2) * 16 + fo4] = a2;
        out[(node + 3) * 16 + fo4] = a3;
    } else {
        a0 = a1 = a2 = a3 = make_float4(0.f, 0.f, 0.f, 0.f);
    }
    // stats: quad-local sums, xor-16 combines the warp's other quad, lanes<16 flush
    float4 s = make_float4(a0.x + a1.x + a2.x + a3.x, a0.y + a1.y + a2.y + a3.y,
                           a0.z + a1.z + a2.z + a3.z, a0.w + a1.w + a2.w + a3.w);
    float4 s2 = make_float4(a0.x*a0.x + a1.x*a1.x + a2.x*a2.x + a3.x*a3.x,
                            a0.y*a0.y + a1.y*a1.y + a2.y*a2.y + a3.y*a3.y,
                            a0.z*a0.z + a1.z*a1.z + a2.z*a2.z + a3.z*a3.z,
                            a0.w*a0.w + a1.w*a1.w + a2.w*a2.w + a3.w*a3.w);
    // correct for inactive quads having bias-initialized accs
    if (!act) { s = make_float4(0, 0, 0, 0); s2 = make_float4(0, 0, 0, 0); }
    s.x += __shfl_xor_sync(~0u, s.x, 16); s2.x += __shfl_xor_sync(~0u, s2.x, 16);
    s.y += __shfl_xor_sync(~0u, s.y, 16); s2.y += __shfl_xor_sync(~0u, s2.y, 16);
    s.z += __shfl_xor_sync(~0u, s.z, 16); s2.z += __shfl_xor_sync(~0u, s2.z, 16);
    s.w += __shfl_xor_sync(~0u, s.w, 16); s2.w += __shfl_xor_sync(~0u, s2.w, 16);
    if ((tid & 31) < 16) {
        atomicAdd(&ss[fo4 * 4 + 0], s.x); atomicAdd(&sq[fo4 * 4 + 0], s2.x);
        atomicAdd(&ss[fo4 * 4 + 1], s.y); atomicAdd(&sq[fo4 * 4 + 1], s2.y);
        atomicAdd(&ss[fo4 * 4 + 2], s.z); atomicAdd(&sq[fo4 * 4 + 2], s2.z);
        atomicAdd(&ss[fo4 * 4 + 3], s.w); atomicAdd(&sq[fo4 * 4 + 3], s2.w);
    }
    __syncthreads();
    if (tid < 64) {
        atomicAdd(&stat[tid], ss[tid]);
        atomicAdd(&stat[64 + tid], sq[tid]);
    }
}

// ---------------- fused BN+ReLU + GEMM + *dinv -> half (4 nodes per thread) ----------------
template <int FI, int FO>
__global__ void k_gemmbn(const float* __restrict__ acc, const float* __restrict__ stat,
                         const float* __restrict__ g, const float* __restrict__ be,
                         const float* __restrict__ W, uint2* __restrict__ out) {
    const int G4 = FO / 4;
    const int NODES = 4 * (256 / G4);
    const int HP = FI + 4;
    __shared__ float4 Ws[FI * G4];
    __shared__ float Hs[NODES * HP];
    __shared__ float sc[FI], sh[FI];
    int tid = threadIdx.x;
    for (int i = tid; i < FI * G4; i += 256) Ws[i] = ((const float4*)W)[i];
    if (tid < FI) {
        const float invn = 1.0f / (float)Nn;
        float mu  = stat[tid] * invn;
        float var = stat[FI + tid] * invn - mu * mu;
        float kk  = g[tid] * rsqrtf(var + BN_EPS);
        sc[tid] = kk;
        sh[tid] = be[tid] - mu * kk;
    }
    __syncthreads();
    int node0 = blockIdx.x * NODES;
    int nv = Nn - node0; if (nv > NODES) nv = NODES;   // multiple of 32
    for (int i = tid; i < nv * (FI / 4); i += 256) {
        int r = i / (FI / 4), q = i % (FI / 4);
        float4 v = ((const float4*)(acc + (node0 + r) * FI))[q];
        int f = q * 4;
        v.x = fmaxf(v.x * sc[f + 0] + sh[f + 0], 0.f);
        v.y = fmaxf(v.y * sc[f + 1] + sh[f + 1], 0.f);
        v.z = fmaxf(v.z * sc[f + 2] + sh[f + 2], 0.f);
        v.w = fmaxf(v.w * sc[f + 3] + sh[f + 3], 0.f);
        *(float4*)&Hs[r * HP + f] = v;
    }
    __syncthreads();
    int np = tid / G4, fo4 = tid % G4;
    int nl0 = np * 4;
    if (nl0 >= nv) return;
    int node = node0 + nl0;
    const float* h0 = &Hs[nl0 * HP];
    float4 a0 = make_float4(0.f, 0.f, 0.f, 0.f);
    float4 a1 = a0, a2 = a0, a3 = a0;
#pragma unroll
    for (int fi = 0; fi < FI; fi++) {
        float4 w = Ws[fi * G4 + fo4];
        float x0 = h0[fi], x1 = h0[HP + fi], x2 = h0[2 * HP + fi], x3 = h0[3 * HP + fi];
        a0.x += x0 * w.x; a0.y += x0 * w.y; a0.z += x0 * w.z; a0.w += x0 * w.w;
        a1.x += x1 * w.x; a1.y += x1 * w.y; a1.z += x1 * w.z; a1.w += x1 * w.w;
        a2.x += x2 * w.x; a2.y += x2 * w.y; a2.z += x2 * w.z; a2.w += x2 * w.w;
        a3.x += x3 * w.x; a3.y += x3 * w.y; a3.z += x3 * w.z; a3.w += x3 * w.w;
    }
    float d0 = g_dinv[node], d1 = g_dinv[node + 1];
    float d2 = g_dinv[node + 2], d3 = g_dinv[node + 3];
    a0.x *= d0; a0.y *= d0; a0.z *= d0; a0.w *= d0;
    a1.x *= d1; a1.y *= d1; a1.z *= d1; a1.w *= d1;
    a2.x *= d2; a2.y *= d2; a2.z *= d2; a2.w *= d2;
    a3.x *= d3; a3.y *= d3; a3.z *= d3; a3.w *= d3;
    __half2 p;
    uint2 u;
    p = __floats2half2_rn(a0.x, a0.y); u.x = *(unsigned*)&p;
    p = __floats2half2_rn(a0.z, a0.w); u.y = *(unsigned*)&p;
    out[node * G4 + fo4] = u;
    p = __floats2half2_rn(a1.x, a1.y); u.x = *(unsigned*)&p;
    p = __floats2half2_rn(a1.z, a1.w); u.y = *(unsigned*)&p;
    out[(node + 1) * G4 + fo4] = u;
    p = __floats2half2_rn(a2.x, a2.y); u.x = *(unsigned*)&p;
    p = __floats2half2_rn(a2.z, a2.w); u.y = *(unsigned*)&p;
    out[(node + 2) * G4 + fo4] = u;
    p = __floats2half2_rn(a3.x, a3.y); u.x = *(unsigned*)&p;
    p = __floats2half2_rn(a3.z, a3.w); u.y = *(unsigned*)&p;
    out[(node + 3) * G4 + fo4] = u;
}

// was[k][h] = sum_c Wg[k][h*16+c]*att_src[h][c]; wad likewise. 128 threads.
__global__ void k_prep(const float* __restrict__ Wg, const float* __restrict__ asrc,
                       const float* __restrict__ adst) {
    int t = threadIdx.x;
    int k = t >> 3, h = t & 7;
    float s1 = 0.f, s2 = 0.f;
#pragma unroll
    for (int c = 0; c < 16; c++) {
        float w = Wg[k * 128 + h * 16 + c];
        s1 += w * asrc[h * 16 + c];
        s2 += w * adst[h * 16 + c];
    }
    g_was[k * 8 + h] = s1;
    g_wad[k * 8 + h] = s2;
}

// fused BN+ReLU(layer3) + h3->half + attention dots. block=256 -> 16 nodes. Nn%16==0.
__global__ void k_bn3att(const float* __restrict__ acc3, const float* __restrict__ stat,
                         const float* __restrict__ g, const float* __restrict__ be) {
    __shared__ float sv[16][17];
    __shared__ float sw[2][16][8];
    int t = threadIdx.x;
    if (t < 128) { sw[0][t >> 3][t & 7] = g_was[t]; sw[1][t >> 3][t & 7] = g_wad[t]; }
    int node0 = blockIdx.x * 16;
    int nl = t >> 4, f = t & 15;
    const float invn = 1.0f / (float)Nn;
    float mu  = stat[f] * invn;
    float var = stat[16 + f] * invn - mu * mu;
    float v = (acc3[(node0 + nl) * 16 + f] - mu) * rsqrtf(var + BN_EPS) * g[f] + be[f];
    v = fmaxf(v, 0.f);
    sv[nl][f] = v;
    __syncthreads();
    if (t < 64) {
        int n2 = t >> 2, q = t & 3;
        __half2 p0 = __floats2half2_rn(sv[n2][q * 4 + 0], sv[n2][q * 4 + 1]);
        __half2 p1 = __floats2half2_rn(sv[n2][q * 4 + 2], sv[n2][q * 4 + 3]);
        uint2 u;
        u.x = *(unsigned*)&p0;
        u.y = *(unsigned*)&p1;
        g_h3h[(node0 + n2) * 4 + q] = u;
    }
    if (t < 128) {
        int n3 = t >> 3, h = t & 7;
        float s1 = 0.f, s2 = 0.f;
#pragma unroll
        for (int k = 0; k < 16; k++) {
            float hv = sv[n3][k];
            s1 += hv * sw[0][k][h];
            s2 += hv * sw[1][k][h];
        }
        g_as[(node0 + n3) * 8 + h] = s1;
        g_ad[(node0 + n3) * 8 + h] = s2;
    }
}

// ---------------- fused GAT (no-max softmax) + full-warp epilogue + deg reset ----------------
__device__ __forceinline__ void gat_step(float l, uint2 u, float& sum, float4& acc) {
    float e = __expf(l);
    float2 f0 = __half22float2(*(const __half2*)&u.x);
    float2 f1 = __half22float2(*(const __half2*)&u.y);
    sum += e;
    acc.x += e * f0.x; acc.y += e * f0.y; acc.z += e * f1.x; acc.w += e * f1.y;
}

__global__ void k_gat(const float* __restrict__ Wg, const float* __restrict__ bg,
                      const int* __restrict__ batch) {
    __shared__ float Wgs[16 * 128];
    __shared__ float buf[8][8][16];     // [warp][head][k]
    for (int i = threadIdx.x; i < 16 * 128; i += blockDim.x) Wgs[i] = Wg[i];
    __syncthreads();
    int lane = threadIdx.x & 31, warp = threadIdx.x >> 5;
    int d = blockIdx.x * 8 + warp;      // grid = Nn/8 exact
    int h = lane >> 2, j = lane & 3;
    float adh = g_ad[d * 8 + h];
    int r0 = d * BUCKET, r1 = r0 + g_deg[d];

    float e0 = __expf(leaky(g_as[d * 8 + h] + adh));
    float sum = e0;
    uint2 su = __ldg(&g_h3h[d * 4 + j]);
    float2 sf0 = __half22float2(*(const __half2*)&su.x);
    float2 sf1 = __half22float2(*(const __half2*)&su.y);
    float4 acc = make_float4(e0 * sf0.x, e0 * sf0.y, e0 * sf1.x, e0 * sf1.y);

    int nb = (r1 - r0) >> 2;
    int k = r0 + (nb << 2);             // tail start
    if (nb >= 2) {
        int p0 = __ldg(&g_csrc[r0]),     p1 = __ldg(&g_csrc[r0 + 1]);
        int p2 = __ldg(&g_csrc[r0 + 2]), p3 = __ldg(&g_csrc[r0 + 3]);
        int q0 = __ldg(&g_csrc[r0 + 4]), q1 = __ldg(&g_csrc[r0 + 5]);
        int q2 = __ldg(&g_csrc[r0 + 6]), q3 = __ldg(&g_csrc[r0 + 7]);
        float la0 = __ldg(&g_as[p0 * 8 + h]), la1 = __ldg(&g_as[p1 * 8 + h]);
        float la2 = __ldg(&g_as[p2 * 8 + h]), la3 = __ldg(&g_as[p3 * 8 + h]);
        uint2 ua0 = __ldg(&g_h3h[p0 * 4 + j]);
        uint2 ua1 = __ldg(&g_h3h[p1 * 4 + j]);
        uint2 ua2 = __ldg(&g_h3h[p2 * 4 + j]);
        uint2 ua3 = __ldg(&g_h3h[p3 * 4 + j]);
        for (int t = 0; t < nb - 1; t++) {
            int c0, c1, c2, c3;
            bool more = (t + 2) < nb;
            if (more) {
                int base = r0 + (t + 2) * 4;
                c0 = __ldg(&g_csrc[base]);     c1 = __ldg(&g_csrc[base + 1]);
                c2 = __ldg(&g_csrc[base + 2]); c3 = __ldg(&g_csrc[base + 3]);
            }
            float lb0 = __ldg(&g_as[q0 * 8 + h]), lb1 = __ldg(&g_as[q1 * 8 + h]);
            float lb2 = __ldg(&g_as[q2 * 8 + h]), lb3 = __ldg(&g_as[q3 * 8 + h]);
            uint2 ub0 = __ldg(&g_h3h[q0 * 4 + j]);
            uint2 ub1 = __ldg(&g_h3h[q1 * 4 + j]);
            uint2 ub2 = __ldg(&g_h3h[q2 * 4 + j]);
            uint2 ub3 = __ldg(&g_h3h[q3 * 4 + j]);
            gat_step(leaky(la0 + adh), ua0, sum, acc);
            gat_step(leaky(la1 + adh), ua1, sum, acc);
            gat_step(leaky(la2 + adh), ua2, sum, acc);
            gat_step(leaky(la3 + adh), ua3, sum, acc);
            la0 = lb0; la1 = lb1; la2 = lb2; la3 = lb3;
            ua0 = ub0; ua1 = ub1; ua2 = ub2; ua3 = ub3;
            if (more) { q0 = c0; q1 = c1; q2 = c2; q3 = c3; }
        }
        gat_step(leaky(la0 + adh), ua0, sum, acc);
        gat_step(leaky(la1 + adh), ua1, sum, acc);
        gat_step(leaky(la2 + adh), ua2, sum, acc);
        gat_step(leaky(la3 + adh), ua3, sum, acc);
    } else if (nb == 1) {
        int p0 = __ldg(&g_csrc[r0]),     p1 = __ldg(&g_csrc[r0 + 1]);
        int p2 = __ldg(&g_csrc[r0 + 2]), p3 = __ldg(&g_csrc[r0 + 3]);
        float la0 = __ldg(&g_as[p0 * 8 + h]), la1 = __ldg(&g_as[p1 * 8 + h]);
        float la2 = __ldg(&g_as[p2 * 8 + h]), la3 = __ldg(&g_as[p3 * 8 + h]);
        uint2 ua0 = __ldg(&g_h3h[p0 * 4 + j]);
        uint2 ua1 = __ldg(&g_h3h[p1 * 4 + j]);
        uint2 ua2 = __ldg(&g_h3h[p2 * 4 + j]);
        uint2 ua3 = __ldg(&g_h3h[p3 * 4 + j]);
        gat_step(leaky(la0 + adh), ua0, sum, acc);
        gat_step(leaky(la1 + adh), ua1, sum, acc);
        gat_step(leaky(la2 + adh), ua2, sum, acc);
        gat_step(leaky(la3 + adh), ua3, sum, acc);
    }
    for (; k < r1; k++) {
        int s = __ldg(&g_csrc[k]);
        float l = leaky(__ldg(&g_as[s * 8 + h]) + adh);
        gat_step(l, __ldg(&g_h3h[s * 4 + j]), sum, acc);
    }
    float sc = 0.125f / sum;
    buf[warp][h][j * 4 + 0] = acc.x * sc;
    buf[warp][h][j * 4 + 1] = acc.y * sc;
    buf[warp][h][j * 4 + 2] = acc.z * sc;
    buf[warp][h][j * 4 + 3] = acc.w * sc;
    __syncwarp();

    if (lane == 0) g_deg[d] = 0;   // reset for next call

    // full-warp mini-GEMM: lane = (c, k-half)
    int c = lane & 15, hf = lane >> 4;
    float s = 0.f;
#pragma unroll
    for (int hh = 0; hh < 8; hh++) {
#pragma unroll
        for (int kq = 0; kq < 8; kq++) {
            int kk = hf * 8 + kq;
            s += buf[warp][hh][kk] * Wgs[kk * 128 + hh * 16 + c];
        }
    }
    s += __shfl_xor_sync(~0u, s, 16);
    __syncwarp();
    if (lane < 16) buf[warp][0][c] = s + bg[c];
    __syncwarp();
    if (lane < 4) {
        float4 hg = *(const float4*)&buf[warp][0][lane * 4];
        red4(((float4*)g_pool) + batch[d] * 4 + lane, hg);
    }
}

// one thread per graph: out[g] = pool[g]@Wf + bf, then zero its pool entries
__global__ void k_final(const float* __restrict__ Wf, const float* __restrict__ bf,
                        float* __restrict__ out) {
    int gg = blockIdx.x * blockDim.x + threadIdx.x;
    if (gg >= Gg) return;
    float p[16];
    float4* pp = (float4*)&g_pool[gg * 16];
#pragma unroll
    for (int q = 0; q < 4; q++) {
        float4 v = pp[q];
        p[q * 4 + 0] = v.x; p[q * 4 + 1] = v.y; p[q * 4 + 2] = v.z; p[q * 4 + 3] = v.w;
        pp[q] = make_float4(0.f, 0.f, 0.f, 0.f);
    }
#pragma unroll
    for (int k = 0; k < 3; k++) {
        float s = bf[k];
#pragma unroll
        for (int c = 0; c < 16; c++) s += p[c] * Wf[c * 3 + k];
        out[gg * 3 + k] = s;
    }
}

// ---------------- launch ----------------
static inline void* symaddr(const void* s) { void* p = nullptr; cudaGetSymbolAddress(&p, s); return p; }

extern "C" void kernel_launch(void* const* d_in, const int* in_sizes, int n_in,
                              void* d_out, int out_size) {
    const float* x       = (const float*)d_in[0];
    const int*   ei      = (const int*)  d_in[1];
    const int*   batch   = (const int*)  d_in[2];
    const float* W1 = (const float*)d_in[3],  *b1 = (const float*)d_in[4];
    const float* g1 = (const float*)d_in[5],  *be1= (const float*)d_in[6];
    const float* W2 = (const float*)d_in[7],  *b2 = (const float*)d_in[8];
    const float* g2 = (const float*)d_in[9],  *be2= (const float*)d_in[10];
    const float* W3 = (const float*)d_in[11], *b3 = (const float*)d_in[12];
    const float* g3 = (const float*)d_in[13], *be3= (const float*)d_in[14];
    const float* Wg = (const float*)d_in[15];
    const float* att_src = (const float*)d_in[16];
    const float* att_dst = (const float*)d_in[17];
    const float* bg = (const float*)d_in[18];
    const float* Wf = (const float*)d_in[19], *bf = (const float*)d_in[20];
    float* out = (float*)d_out;
    const int E = in_sizes[1] / 2;

    float* axp  = (float*)symaddr(g_axp);
    float* acc1 = (float*)symaddr(g_acc1);
    float* acc2 = (float*)symaddr(g_acc2);
    float* acc3 = (float*)symaddr(g_acc3);
    float* bn   = (float*)symaddr(g_bn);
    uint4* xh   = (uint4*)symaddr(g_xh);
    uint2* t2h  = (uint2*)symaddr(g_t2h);
    uint2* t3h  = (uint2*)symaddr(g_t3h);

    const int B = 256;
    // ---- bucket adjacency build ----
    k_fillb<<<(E / 8 + B) / B, B>>>(ei, E);
    k_dinvconvx<<<(Nn * 4 + B - 1) / B, B>>>(x);

    // ---- GCN layer 1: aggregate x' (half), 4-node GEMM 20->64 (+stats) ----
    k_gcn<4, false><<<(Nn + 63) / 64, B>>>(xh, nullptr, (float4*)axp, nullptr);
    k_gemm1<<<(Nn + 63) / 64, B>>>(axp, W1, b1, (float4*)acc1, bn + 0);

    // ---- GCN layer 2: fused BN1+ReLU+GEMM 64->32 (4-node), aggregate (+stats) ----
    k_gemmbn<64, 32><<<(Nn + 127) / 128, B>>>(acc1, bn + 0, g1, be1, W2, t2h);
    k_gcn<4, true><<<(Nn + 63) / 64, B>>>((const uint4*)t2h, b2, (float4*)acc2, bn + 128);

    // ---- GCN layer 3: fused BN2+ReLU+GEMM 32->16 (4-node), aggregate (+stats) ----
    k_gemmbn<32, 16><<<(Nn + 255) / 256, B>>>(acc2, bn + 128, g2, be2, W3, t3h);
    k_gcn<2, true><<<(Nn + 127) / 128, B>>>((const uint4*)t3h, b3, (float4*)acc3, bn + 256);

    // ---- BN3 + attention dots fused, then no-max GAT (+deg reset) ----
    k_prep<<<1, 128>>>(Wg, att_src, att_dst);
    k_bn3att<<<Nn / 16, B>>>(acc3, bn + 256, g3, be3);
    k_gat<<<Nn / 8, B>>>(Wg, bg, batch);

    // ---- classifier (+pool reset) ----
    k_final<<<(Gg + B - 1) / B, B>>>(Wf, bf, out);
}